// round 1
// baseline (speedup 1.0000x reference)
#include <cuda_runtime.h>
#include <math.h>

// Problem constants
constexpr int C_DM = 512;
constexpr int C_H  = 8;
constexpr int C_B  = 8;
constexpr int C_SQ = 1024;
constexpr int C_SK = 1024;

// GEMM tiling
constexpr int BM = 128;
constexpr int BN = 128;
constexpr int BK = 8;
constexpr int TM = 8;
constexpr int TN = 8;

// Scratch (allocation-free rule: __device__ globals)
__device__ float g_Ql[C_B * C_SQ * C_DM];
__device__ float g_Kl[C_B * C_SK * C_DM];
__device__ float g_Vl[C_B * C_SK * C_DM];
__device__ float g_S [C_B * (size_t)C_SQ * C_SK];
__device__ float g_head[C_B * C_SQ * C_DM];
__device__ float g_Weff[C_DM * C_DM];

// ---------------------------------------------------------------------------
// Wl reduction: Weff[d, j] = sum_h Wl[h*DM + d, j]
// (because multi = tile(head, H), Y = head @ Weff + bl)
// ---------------------------------------------------------------------------
__global__ void wl_reduce_kernel(const float* __restrict__ Wl,
                                 float* __restrict__ Weff) {
    int idx = blockIdx.x * blockDim.x + threadIdx.x;   // 0 .. DM*DM-1
    int d = idx / C_DM;
    int j = idx % C_DM;
    float s = 0.f;
#pragma unroll
    for (int h = 0; h < C_H; h++)
        s += Wl[((size_t)(h * C_DM + d)) * C_DM + j];
    Weff[idx] = s;
}

// ---------------------------------------------------------------------------
// Tiled SGEMM: C = op(A) * op(B) [+ epilogue]
//   A is [M,K] row-major (lda = K stride).
//   TB=false: B is [K,N] row-major.  TB=true: B is [N,K] row-major (C=A*B^T).
//   MODE 0: C = acc
//   MODE 1: C = acc + bias[col]
//   MODE 2: C = acc*invscale + (float)mask[bz*maskStride + col] * (-1e9)
// All of M,K divisible by 128/8; N divisible by 128. No bounds checks.
// ---------------------------------------------------------------------------
template <bool TB, int MODE>
__global__ __launch_bounds__(256)
void sgemm_kernel(const float* __restrict__ Ag, const float* __restrict__ Bg,
                  float* __restrict__ Cg,
                  int M, int N, int K, int lda, int ldb, int ldc,
                  long long sA, long long sB, long long sC,
                  const float* __restrict__ bias,
                  const int* __restrict__ mask, int maskStride,
                  float invscale) {
    __shared__ float As[BK][BM];
    __shared__ float Bs[BK][BN];

    const int bz = blockIdx.z;
    const float* A = Ag + bz * sA;
    const float* Bp = Bg + bz * sB;
    float* C = Cg + bz * sC;

    const int bm = blockIdx.y * BM;
    const int bn = blockIdx.x * BN;
    const int tid = threadIdx.x;           // 0..255
    const int tx = tid & 15;               // 16 cols of threads
    const int ty = tid >> 4;               // 16 rows of threads

    // A tile load mapping: 128 rows x 8 k, one float4 per thread
    const int arow = tid >> 1;
    const int acol = (tid & 1) * 4;
    // B tile load mapping
    const int brow = TB ? (tid >> 1) : (tid >> 5);
    const int bcol = TB ? ((tid & 1) * 4) : ((tid & 31) * 4);

    float acc[TM][TN];
#pragma unroll
    for (int i = 0; i < TM; i++)
#pragma unroll
        for (int j = 0; j < TN; j++) acc[i][j] = 0.f;

    for (int k0 = 0; k0 < K; k0 += BK) {
        // ---- load A tile (transpose into [k][m]) ----
        float4 av = *reinterpret_cast<const float4*>(
            &A[(size_t)(bm + arow) * lda + k0 + acol]);
        As[acol + 0][arow] = av.x;
        As[acol + 1][arow] = av.y;
        As[acol + 2][arow] = av.z;
        As[acol + 3][arow] = av.w;

        // ---- load B tile into [k][n] ----
        if (TB) {
            float4 bv = *reinterpret_cast<const float4*>(
                &Bp[(size_t)(bn + brow) * ldb + k0 + bcol]);
            Bs[bcol + 0][brow] = bv.x;
            Bs[bcol + 1][brow] = bv.y;
            Bs[bcol + 2][brow] = bv.z;
            Bs[bcol + 3][brow] = bv.w;
        } else {
            float4 bv = *reinterpret_cast<const float4*>(
                &Bp[(size_t)(k0 + brow) * ldb + bn + bcol]);
            *reinterpret_cast<float4*>(&Bs[brow][bcol]) = bv;
        }
        __syncthreads();

#pragma unroll
        for (int kk = 0; kk < BK; kk++) {
            float a[TM], b[TN];
            float4 a0 = *reinterpret_cast<const float4*>(&As[kk][ty * TM]);
            float4 a1 = *reinterpret_cast<const float4*>(&As[kk][ty * TM + 4]);
            float4 b0 = *reinterpret_cast<const float4*>(&Bs[kk][tx * TN]);
            float4 b1 = *reinterpret_cast<const float4*>(&Bs[kk][tx * TN + 4]);
            a[0] = a0.x; a[1] = a0.y; a[2] = a0.z; a[3] = a0.w;
            a[4] = a1.x; a[5] = a1.y; a[6] = a1.z; a[7] = a1.w;
            b[0] = b0.x; b[1] = b0.y; b[2] = b0.z; b[3] = b0.w;
            b[4] = b1.x; b[5] = b1.y; b[6] = b1.z; b[7] = b1.w;
#pragma unroll
            for (int i = 0; i < TM; i++)
#pragma unroll
                for (int j = 0; j < TN; j++)
                    acc[i][j] = fmaf(a[i], b[j], acc[i][j]);
        }
        __syncthreads();
    }

    // ---- epilogue ----
#pragma unroll
    for (int i = 0; i < TM; i++) {
        int row = bm + ty * TM + i;
#pragma unroll
        for (int j = 0; j < TN; j += 4) {
            int col = bn + tx * TN + j;
            float4 v;
            v.x = acc[i][j + 0];
            v.y = acc[i][j + 1];
            v.z = acc[i][j + 2];
            v.w = acc[i][j + 3];
            if (MODE == 1) {
                v.x += bias[col + 0];
                v.y += bias[col + 1];
                v.z += bias[col + 2];
                v.w += bias[col + 3];
            } else if (MODE == 2) {
                const int* mrow = mask + (size_t)bz * maskStride;
                v.x = v.x * invscale + (float)mrow[col + 0] * -1e9f;
                v.y = v.y * invscale + (float)mrow[col + 1] * -1e9f;
                v.z = v.z * invscale + (float)mrow[col + 2] * -1e9f;
                v.w = v.w * invscale + (float)mrow[col + 3] * -1e9f;
            }
            *reinterpret_cast<float4*>(&C[(size_t)row * ldc + col]) = v;
        }
    }
}

// ---------------------------------------------------------------------------
// Row softmax over SK=1024 elems. 256 threads, 4 elems/thread.
// Writes result back to scratch S (consumed by the AV GEMM) and, if
// writeAtt, replicates into all H slots of att_ws in d_out.
// ---------------------------------------------------------------------------
__global__ __launch_bounds__(256)
void softmax_kernel(float* __restrict__ S, float* __restrict__ attOut,
                    int writeAtt) {
    const int q = blockIdx.x;
    const int b = blockIdx.y;
    const int tid = threadIdx.x;

    float* row = S + ((size_t)b * C_SQ + q) * C_SK;
    float4 x = *reinterpret_cast<const float4*>(&row[tid * 4]);

    __shared__ float red[256];
    float m = fmaxf(fmaxf(x.x, x.y), fmaxf(x.z, x.w));
    red[tid] = m;
    __syncthreads();
#pragma unroll
    for (int s = 128; s > 0; s >>= 1) {
        if (tid < s) red[tid] = fmaxf(red[tid], red[tid + s]);
        __syncthreads();
    }
    const float rowmax = red[0];
    __syncthreads();

    x.x = expf(x.x - rowmax);
    x.y = expf(x.y - rowmax);
    x.z = expf(x.z - rowmax);
    x.w = expf(x.w - rowmax);

    red[tid] = x.x + x.y + x.z + x.w;
    __syncthreads();
#pragma unroll
    for (int s = 128; s > 0; s >>= 1) {
        if (tid < s) red[tid] += red[tid + s];
        __syncthreads();
    }
    const float inv = 1.f / red[0];
    __syncthreads();

    x.x *= inv; x.y *= inv; x.z *= inv; x.w *= inv;
    *reinterpret_cast<float4*>(&row[tid * 4]) = x;

    if (writeAtt) {
        size_t base = ((size_t)b * C_H * C_SQ + q) * C_SK + tid * 4;
#pragma unroll
        for (int h = 0; h < C_H; h++)
            *reinterpret_cast<float4*>(&attOut[base + (size_t)h * C_SQ * C_SK]) = x;
    }
}

// ---------------------------------------------------------------------------
// Launch
// ---------------------------------------------------------------------------
extern "C" void kernel_launch(void* const* d_in, const int* in_sizes, int n_in,
                              void* d_out, int out_size) {
    const float* Q    = (const float*)d_in[0];
    const float* K    = (const float*)d_in[1];
    const float* V    = (const float*)d_in[2];
    const int*   mask = (const int*)  d_in[3];
    const float* Wq   = (const float*)d_in[4];
    const float* bq   = (const float*)d_in[5];
    const float* Wk   = (const float*)d_in[6];
    const float* bk   = (const float*)d_in[7];
    const float* Wv   = (const float*)d_in[8];
    const float* bv   = (const float*)d_in[9];
    const float* Wl   = (const float*)d_in[10];
    const float* bl   = (const float*)d_in[11];

    float *pQl, *pKl, *pVl, *pS, *pHead, *pWeff;
    cudaGetSymbolAddress((void**)&pQl,   g_Ql);
    cudaGetSymbolAddress((void**)&pKl,   g_Kl);
    cudaGetSymbolAddress((void**)&pVl,   g_Vl);
    cudaGetSymbolAddress((void**)&pS,    g_S);
    cudaGetSymbolAddress((void**)&pHead, g_head);
    cudaGetSymbolAddress((void**)&pWeff, g_Weff);

    float* Y = (float*)d_out;
    const long long ySize   = (long long)C_B * C_SQ * C_DM;           // 4,194,304
    const long long attSize = (long long)C_B * C_H * C_SQ * C_SK;     // 67,108,864
    const int writeAtt = ((long long)out_size >= ySize + attSize) ? 1 : 0;
    float* attOut = Y + ySize;

    const float invscale = 1.0f / sqrtf((float)C_DM);
    const dim3 blk(256);

    // Weff = sum over H of Wl blocks
    wl_reduce_kernel<<<(C_DM * C_DM) / 256, 256>>>(Wl, pWeff);

    // Projections: [B*SQ, DM] x [DM, DM] + bias
    {
        dim3 grid(C_DM / BN, (C_B * C_SQ) / BM, 1);
        sgemm_kernel<false, 1><<<grid, blk>>>(Q, Wq, pQl,
            C_B * C_SQ, C_DM, C_DM, C_DM, C_DM, C_DM, 0, 0, 0,
            bq, nullptr, 0, 0.f);
        sgemm_kernel<false, 1><<<grid, blk>>>(K, Wk, pKl,
            C_B * C_SK, C_DM, C_DM, C_DM, C_DM, C_DM, 0, 0, 0,
            bk, nullptr, 0, 0.f);
        sgemm_kernel<false, 1><<<grid, blk>>>(V, Wv, pVl,
            C_B * C_SK, C_DM, C_DM, C_DM, C_DM, C_DM, 0, 0, 0,
            bv, nullptr, 0, 0.f);
    }

    // scores = Ql @ Kl^T * invscale + mask * (-1e9), batched over B
    {
        dim3 grid(C_SK / BN, C_SQ / BM, C_B);
        sgemm_kernel<true, 2><<<grid, blk>>>(pQl, pKl, pS,
            C_SQ, C_SK, C_DM, C_DM, C_DM, C_SK,
            (long long)C_SQ * C_DM, (long long)C_SK * C_DM,
            (long long)C_SQ * C_SK,
            nullptr, mask, C_SK, invscale);
    }

    // softmax (+ write att_ws replicated across H)
    {
        dim3 grid(C_SQ, C_B);
        softmax_kernel<<<grid, blk>>>(pS, attOut, writeAtt);
    }

    // head = att @ Vl, batched over B
    {
        dim3 grid(C_DM / BN, C_SQ / BM, C_B);
        sgemm_kernel<false, 0><<<grid, blk>>>(pS, pVl, pHead,
            C_SQ, C_DM, C_SK, C_SK, C_DM, C_DM,
            (long long)C_SQ * C_SK, (long long)C_SK * C_DM,
            (long long)C_SQ * C_DM,
            nullptr, nullptr, 0, 0.f);
    }

    // Y = head @ Weff + bl
    {
        dim3 grid(C_DM / BN, (C_B * C_SQ) / BM, 1);
        sgemm_kernel<false, 1><<<grid, blk>>>(pHead, pWeff, Y,
            C_B * C_SQ, C_DM, C_DM, C_DM, C_DM, C_DM, 0, 0, 0,
            bl, nullptr, 0, 0.f);
    }
}

// round 2
// speedup vs baseline: 2.2864x; 2.2864x over previous
#include <cuda_runtime.h>
#include <math.h>
#include <stdint.h>

// Problem constants
constexpr int C_DM = 512;
constexpr int C_H  = 8;
constexpr int C_B  = 8;
constexpr int C_SQ = 1024;
constexpr int C_SK = 1024;

// GEMM tiling
constexpr int BM = 128;
constexpr int BN = 128;
constexpr int BK = 16;
constexpr int AS = BM + 4;   // 132 words, smem row stride (k-major A)
constexpr int BS = BN + 4;   // 132 words, smem row stride (k-major B)

// Scratch (allocation-free rule: __device__ globals)
__device__ float g_Ql[C_B * C_SQ * C_DM];
__device__ float g_Kl[C_B * C_SK * C_DM];
__device__ float g_Vl[C_B * C_SK * C_DM];
__device__ float g_S [C_B * (size_t)C_SQ * C_SK];
__device__ float g_head[C_B * C_SQ * C_DM];
__device__ float g_Weff[C_DM * C_DM];

__device__ __forceinline__ uint32_t f2tf32(float f) {
    uint32_t u;
    asm("cvt.rna.tf32.f32 %0, %1;" : "=r"(u) : "f"(f));
    return u;
}

__device__ __forceinline__ void mma_tf32(float c[4],
                                         const uint32_t a[4],
                                         const uint32_t b[2]) {
    asm volatile(
        "mma.sync.aligned.m16n8k8.row.col.f32.tf32.tf32.f32 "
        "{%0,%1,%2,%3}, {%4,%5,%6,%7}, {%8,%9}, {%0,%1,%2,%3};"
        : "+f"(c[0]), "+f"(c[1]), "+f"(c[2]), "+f"(c[3])
        : "r"(a[0]), "r"(a[1]), "r"(a[2]), "r"(a[3]),
          "r"(b[0]), "r"(b[1]));
}

// ---------------------------------------------------------------------------
// Wl reduction: Weff[d, j] = sum_h Wl[h*DM + d, j]
// ---------------------------------------------------------------------------
__global__ void wl_reduce_kernel(const float* __restrict__ Wl,
                                 float* __restrict__ Weff) {
    int idx = blockIdx.x * blockDim.x + threadIdx.x;
    int d = idx / C_DM;
    int j = idx % C_DM;
    float s = 0.f;
#pragma unroll
    for (int h = 0; h < C_H; h++)
        s += Wl[((size_t)(h * C_DM + d)) * C_DM + j];
    Weff[idx] = s;
}

// ---------------------------------------------------------------------------
// TF32 tensor-core GEMM: C = op(A) * op(B) [+ epilogue]
//   A [M,K] row-major.  TB=false: B [K,N] row-major.  TB=true: B [N,K] (C=A*B^T)
//   MODE 0: C = acc ; MODE 1: C = acc + bias[col]
//   MODE 2: C = acc*invscale + (float)mask[bz*maskStride + col] * (-1e9)
// M%128==0, N%128==0, K%16==0. 256 threads, 8 warps (2x4), 64x32 warp tiles.
// ---------------------------------------------------------------------------
template <bool TB, int MODE>
__global__ __launch_bounds__(256)
void gemm_tf32(const float* __restrict__ Ag, const float* __restrict__ Bg,
               float* __restrict__ Cg,
               int M, int N, int K, int lda, int ldb, int ldc,
               long long sA, long long sB, long long sC,
               const float* __restrict__ bias,
               const int* __restrict__ mask, int maskStride,
               float invscale) {
    __shared__ __align__(16) uint32_t Ash[2][BK][AS];
    __shared__ __align__(16) uint32_t Bsh[2][BK][BS];

    const int bz = blockIdx.z;
    const float* A  = Ag + bz * sA;
    const float* Bp = Bg + bz * sB;
    float* C = Cg + bz * sC;

    const int bm = blockIdx.y * BM;
    const int bn = blockIdx.x * BN;
    const int tid  = threadIdx.x;
    const int lane = tid & 31;
    const int warp = tid >> 5;
    const int wm = (warp & 1) * 64;   // warp M offset (2 warps in M)
    const int wn = (warp >> 1) * 32;  // warp N offset (4 warps in N)

    // A gmem->smem mapping: 128x16 tile, 2 float4/thread, transpose to [k][m]
    const int ar = tid >> 2;          // row 0..63 (+64 second iter)
    const int ac = (tid & 3) * 4;     // k col
    // B gmem->smem (TB=false): 16x128 tile, 2 float4/thread, keep [k][n]
    const int br = tid >> 5;          // row 0..7 (+8 second iter)
    const int bc = (tid & 31) * 4;    // n col

    auto ldgA = [&](int k0, float4 pa[2]) {
#pragma unroll
        for (int it = 0; it < 2; it++)
            pa[it] = *reinterpret_cast<const float4*>(
                &A[(size_t)(bm + ar + it * 64) * lda + k0 + ac]);
    };
    auto stsA = [&](int st, const float4 pa[2]) {
#pragma unroll
        for (int it = 0; it < 2; it++) {
            int row = ar + it * 64;
            Ash[st][ac + 0][row] = f2tf32(pa[it].x);
            Ash[st][ac + 1][row] = f2tf32(pa[it].y);
            Ash[st][ac + 2][row] = f2tf32(pa[it].z);
            Ash[st][ac + 3][row] = f2tf32(pa[it].w);
        }
    };
    auto ldgB = [&](int k0, float4 pb[2]) {
#pragma unroll
        for (int it = 0; it < 2; it++) {
            if (TB) {
                // B [N,K]: load rows of N, cols of K (like A)
                pb[it] = *reinterpret_cast<const float4*>(
                    &Bp[(size_t)(bn + ar + it * 64) * ldb + k0 + ac]);
            } else {
                pb[it] = *reinterpret_cast<const float4*>(
                    &Bp[(size_t)(k0 + br + it * 8) * ldb + bn + bc]);
            }
        }
    };
    auto stsB = [&](int st, const float4 pb[2]) {
#pragma unroll
        for (int it = 0; it < 2; it++) {
            if (TB) {
                int row = ar + it * 64;  // n index
                Bsh[st][ac + 0][row] = f2tf32(pb[it].x);
                Bsh[st][ac + 1][row] = f2tf32(pb[it].y);
                Bsh[st][ac + 2][row] = f2tf32(pb[it].z);
                Bsh[st][ac + 3][row] = f2tf32(pb[it].w);
            } else {
                uint4 u;
                u.x = f2tf32(pb[it].x);
                u.y = f2tf32(pb[it].y);
                u.z = f2tf32(pb[it].z);
                u.w = f2tf32(pb[it].w);
                *reinterpret_cast<uint4*>(&Bsh[st][br + it * 8][bc]) = u;
            }
        }
    };

    float acc[4][4][4];
#pragma unroll
    for (int mt = 0; mt < 4; mt++)
#pragma unroll
        for (int nt = 0; nt < 4; nt++)
#pragma unroll
            for (int r = 0; r < 4; r++) acc[mt][nt][r] = 0.f;

    float4 pa[2], pb[2];
    ldgA(0, pa);
    ldgB(0, pb);
    stsA(0, pa);
    stsB(0, pb);
    __syncthreads();

    int stage = 0;
    for (int k0 = 0; k0 < K; k0 += BK) {
        const bool has_next = (k0 + BK) < K;
        if (has_next) {
            ldgA(k0 + BK, pa);
            ldgB(k0 + BK, pb);
        }

        // compute on current stage: 2 k-groups of 8
#pragma unroll
        for (int kg = 0; kg < 2; kg++) {
            const int kb = kg * 8 + (lane & 3);
            uint32_t a[4][4], b[4][2];
#pragma unroll
            for (int mt = 0; mt < 4; mt++) {
                const int m = wm + mt * 16 + (lane >> 2);
                a[mt][0] = Ash[stage][kb][m];
                a[mt][1] = Ash[stage][kb][m + 8];
                a[mt][2] = Ash[stage][kb + 4][m];
                a[mt][3] = Ash[stage][kb + 4][m + 8];
            }
#pragma unroll
            for (int nt = 0; nt < 4; nt++) {
                const int n = wn + nt * 8 + (lane >> 2);
                b[nt][0] = Bsh[stage][kb][n];
                b[nt][1] = Bsh[stage][kb + 4][n];
            }
#pragma unroll
            for (int mt = 0; mt < 4; mt++)
#pragma unroll
                for (int nt = 0; nt < 4; nt++)
                    mma_tf32(acc[mt][nt], a[mt], b[nt]);
        }

        if (has_next) {
            stsA(stage ^ 1, pa);
            stsB(stage ^ 1, pb);
            __syncthreads();
            stage ^= 1;
        }
    }

    // ---- epilogue: per mma tile, lane owns (r, c),(r, c+1),(r+8, c),(r+8, c+1)
#pragma unroll
    for (int mt = 0; mt < 4; mt++) {
        const int row0 = bm + wm + mt * 16 + (lane >> 2);
#pragma unroll
        for (int nt = 0; nt < 4; nt++) {
            const int col = bn + wn + nt * 8 + (lane & 3) * 2;
#pragma unroll
            for (int half = 0; half < 2; half++) {
                const int row = row0 + half * 8;
                float v0 = acc[mt][nt][half * 2 + 0];
                float v1 = acc[mt][nt][half * 2 + 1];
                if (MODE == 1) {
                    v0 += bias[col];
                    v1 += bias[col + 1];
                } else if (MODE == 2) {
                    const int* mrow = mask + (size_t)bz * maskStride;
                    v0 = v0 * invscale + (float)mrow[col]     * -1e9f;
                    v1 = v1 * invscale + (float)mrow[col + 1] * -1e9f;
                }
                float2 st; st.x = v0; st.y = v1;
                *reinterpret_cast<float2*>(&C[(size_t)row * ldc + col]) = st;
            }
        }
    }
}

// ---------------------------------------------------------------------------
// Row softmax over SK=1024. 256 threads, 4 elems/thread. Optionally replicate
// att into all H slots of att_ws.
// ---------------------------------------------------------------------------
__global__ __launch_bounds__(256)
void softmax_kernel(float* __restrict__ S, float* __restrict__ attOut,
                    int writeAtt) {
    const int q = blockIdx.x;
    const int b = blockIdx.y;
    const int tid = threadIdx.x;

    float* row = S + ((size_t)b * C_SQ + q) * C_SK;
    float4 x = *reinterpret_cast<const float4*>(&row[tid * 4]);

    __shared__ float red[256];
    float m = fmaxf(fmaxf(x.x, x.y), fmaxf(x.z, x.w));
    red[tid] = m;
    __syncthreads();
#pragma unroll
    for (int s = 128; s > 0; s >>= 1) {
        if (tid < s) red[tid] = fmaxf(red[tid], red[tid + s]);
        __syncthreads();
    }
    const float rowmax = red[0];
    __syncthreads();

    x.x = expf(x.x - rowmax);
    x.y = expf(x.y - rowmax);
    x.z = expf(x.z - rowmax);
    x.w = expf(x.w - rowmax);

    red[tid] = x.x + x.y + x.z + x.w;
    __syncthreads();
#pragma unroll
    for (int s = 128; s > 0; s >>= 1) {
        if (tid < s) red[tid] += red[tid + s];
        __syncthreads();
    }
    const float inv = 1.f / red[0];
    __syncthreads();

    x.x *= inv; x.y *= inv; x.z *= inv; x.w *= inv;
    *reinterpret_cast<float4*>(&row[tid * 4]) = x;

    if (writeAtt) {
        size_t base = ((size_t)b * C_H * C_SQ + q) * C_SK + tid * 4;
#pragma unroll
        for (int h = 0; h < C_H; h++)
            *reinterpret_cast<float4*>(&attOut[base + (size_t)h * C_SQ * C_SK]) = x;
    }
}

// ---------------------------------------------------------------------------
// Launch
// ---------------------------------------------------------------------------
extern "C" void kernel_launch(void* const* d_in, const int* in_sizes, int n_in,
                              void* d_out, int out_size) {
    const float* Q    = (const float*)d_in[0];
    const float* K    = (const float*)d_in[1];
    const float* V    = (const float*)d_in[2];
    const int*   mask = (const int*)  d_in[3];
    const float* Wq   = (const float*)d_in[4];
    const float* bq   = (const float*)d_in[5];
    const float* Wk   = (const float*)d_in[6];
    const float* bk   = (const float*)d_in[7];
    const float* Wv   = (const float*)d_in[8];
    const float* bv   = (const float*)d_in[9];
    const float* Wl   = (const float*)d_in[10];
    const float* bl   = (const float*)d_in[11];

    float *pQl, *pKl, *pVl, *pS, *pHead, *pWeff;
    cudaGetSymbolAddress((void**)&pQl,   g_Ql);
    cudaGetSymbolAddress((void**)&pKl,   g_Kl);
    cudaGetSymbolAddress((void**)&pVl,   g_Vl);
    cudaGetSymbolAddress((void**)&pS,    g_S);
    cudaGetSymbolAddress((void**)&pHead, g_head);
    cudaGetSymbolAddress((void**)&pWeff, g_Weff);

    float* Y = (float*)d_out;
    const long long ySize   = (long long)C_B * C_SQ * C_DM;
    const long long attSize = (long long)C_B * C_H * C_SQ * C_SK;
    const int writeAtt = ((long long)out_size >= ySize + attSize) ? 1 : 0;
    float* attOut = Y + ySize;

    const float invscale = 1.0f / sqrtf((float)C_DM);
    const dim3 blk(256);

    wl_reduce_kernel<<<(C_DM * C_DM) / 256, 256>>>(Wl, pWeff);

    // Projections: [B*S, DM] x [DM, DM] + bias
    {
        dim3 grid(C_DM / BN, (C_B * C_SQ) / BM, 1);
        gemm_tf32<false, 1><<<grid, blk>>>(Q, Wq, pQl,
            C_B * C_SQ, C_DM, C_DM, C_DM, C_DM, C_DM, 0, 0, 0,
            bq, nullptr, 0, 0.f);
        gemm_tf32<false, 1><<<grid, blk>>>(K, Wk, pKl,
            C_B * C_SK, C_DM, C_DM, C_DM, C_DM, C_DM, 0, 0, 0,
            bk, nullptr, 0, 0.f);
        gemm_tf32<false, 1><<<grid, blk>>>(V, Wv, pVl,
            C_B * C_SK, C_DM, C_DM, C_DM, C_DM, C_DM, 0, 0, 0,
            bv, nullptr, 0, 0.f);
    }

    // scores = Ql @ Kl^T * invscale + mask * (-1e9)
    {
        dim3 grid(C_SK / BN, C_SQ / BM, C_B);
        gemm_tf32<true, 2><<<grid, blk>>>(pQl, pKl, pS,
            C_SQ, C_SK, C_DM, C_DM, C_DM, C_SK,
            (long long)C_SQ * C_DM, (long long)C_SK * C_DM,
            (long long)C_SQ * C_SK,
            nullptr, mask, C_SK, invscale);
    }

    // softmax (+ replicate att into att_ws)
    {
        dim3 grid(C_SQ, C_B);
        softmax_kernel<<<grid, blk>>>(pS, attOut, writeAtt);
    }

    // head = att @ Vl
    {
        dim3 grid(C_DM / BN, C_SQ / BM, C_B);
        gemm_tf32<false, 0><<<grid, blk>>>(pS, pVl, pHead,
            C_SQ, C_DM, C_SK, C_SK, C_DM, C_DM,
            (long long)C_SQ * C_SK, (long long)C_SK * C_DM,
            (long long)C_SQ * C_DM,
            nullptr, nullptr, 0, 0.f);
    }

    // Y = head @ Weff + bl
    {
        dim3 grid(C_DM / BN, (C_B * C_SQ) / BM, 1);
        gemm_tf32<false, 1><<<grid, blk>>>(pHead, pWeff, Y,
            C_B * C_SQ, C_DM, C_DM, C_DM, C_DM, C_DM, 0, 0, 0,
            bl, nullptr, 0, 0.f);
    }
}

// round 4
// speedup vs baseline: 2.6807x; 1.1724x over previous
#include <cuda_runtime.h>
#include <math.h>
#include <stdint.h>

// Problem constants
constexpr int C_DM = 512;
constexpr int C_H  = 8;
constexpr int C_B  = 8;
constexpr int C_SQ = 1024;
constexpr int C_SK = 1024;

// GEMM tiling: CTA 128x128x16, 4 warps (2x2), warp tile 64x64
constexpr int BM = 128;
constexpr int BN = 128;
constexpr int BK = 16;
constexpr int SA = 20;                        // smem row stride in words (16 data + 4 pad)
constexpr int SMEM_WORDS = 2 * BM * SA * 2;   // 2 operands x 2 stages
constexpr int SMEM_BYTES = SMEM_WORDS * 4;    // 40960

// Scratch (allocation-free rule: __device__ globals)
__device__ float g_Ql [C_B * C_SQ * C_DM];
__device__ float g_Kl [C_B * C_SK * C_DM];
__device__ float g_Vl [C_B * C_SK * C_DM];
__device__ float g_VlT[C_B * C_SK * C_DM];
__device__ float g_S  [C_B * (size_t)C_SQ * C_SK];
__device__ float g_head[C_B * C_SQ * C_DM];
__device__ float g_Weff [C_DM * C_DM];
__device__ float g_WqT  [C_DM * C_DM];
__device__ float g_WkT  [C_DM * C_DM];
__device__ float g_WvT  [C_DM * C_DM];
__device__ float g_WeffT[C_DM * C_DM];

__device__ __forceinline__ uint32_t f2tf32(float f) {
    uint32_t u;
    asm("cvt.rna.tf32.f32 %0, %1;" : "=r"(u) : "f"(f));
    return u;
}

__device__ __forceinline__ float roundtf(float f) {
    return __uint_as_float(f2tf32(f));
}

__device__ __forceinline__ void mma_tf32(float c[4],
                                         const uint32_t a[4],
                                         const uint32_t b[2]) {
    asm volatile(
        "mma.sync.aligned.m16n8k8.row.col.f32.tf32.tf32.f32 "
        "{%0,%1,%2,%3}, {%4,%5,%6,%7}, {%8,%9}, {%0,%1,%2,%3};"
        : "+f"(c[0]), "+f"(c[1]), "+f"(c[2]), "+f"(c[3])
        : "r"(a[0]), "r"(a[1]), "r"(a[2]), "r"(a[3]),
          "r"(b[0]), "r"(b[1]));
}

// ---------------------------------------------------------------------------
// Wl reduction: Weff[d, j] = sum_h Wl[h*DM + d, j]
// ---------------------------------------------------------------------------
__global__ void wl_reduce_kernel(const float* __restrict__ Wl,
                                 float* __restrict__ Weff) {
    int idx = blockIdx.x * blockDim.x + threadIdx.x;
    int d = idx / C_DM;
    int j = idx % C_DM;
    float s = 0.f;
#pragma unroll
    for (int h = 0; h < C_H; h++)
        s += Wl[((size_t)(h * C_DM + d)) * C_DM + j];
    Weff[idx] = s;
}

// ---------------------------------------------------------------------------
// Tiled transpose: out[c][r] = in[r][c], batched over z. R,C multiples of 32.
// RND: round output to tf32.
// ---------------------------------------------------------------------------
template <bool RND>
__global__ __launch_bounds__(256)
void transpose_kernel(const float* __restrict__ in, float* __restrict__ out,
                      int R, int C) {
    __shared__ float t[32][33];
    const size_t zoff = (size_t)blockIdx.z * R * C;
    in  += zoff;
    out += zoff;
    int c = blockIdx.x * 32 + threadIdx.x;
    int r = blockIdx.y * 32 + threadIdx.y;
#pragma unroll
    for (int i = 0; i < 4; i++)
        t[threadIdx.y + i * 8][threadIdx.x] = in[(size_t)(r + i * 8) * C + c];
    __syncthreads();
    int co = blockIdx.y * 32 + threadIdx.x;
    int ro = blockIdx.x * 32 + threadIdx.y;
#pragma unroll
    for (int i = 0; i < 4; i++) {
        float v = t[threadIdx.x][threadIdx.y + i * 8];
        if (RND) v = roundtf(v);
        out[(size_t)(ro + i * 8) * R + co] = v;
    }
}

// ---------------------------------------------------------------------------
// TF32 tensor-core GEMM: C[M,N] = A[M,K] * B[N,K]^T, batched (z).
//   MODE 0: C = acc ; MODE 1: C = acc + bias[col]
//   MODE 2: C = acc*invscale + (float)mask[bz*maskStride + col] * (-1e9)
//   RND : round result to tf32 (when it feeds a later GEMM)
//   CVTA: A operand is raw fp32, convert to tf32 on the smem store path.
//         (B operands are always pre-rounded in gmem.)
// M%128==0, N%128==0, K%16==0. 128 threads, 4 warps (2x2) of 64x64.
// ---------------------------------------------------------------------------
template <int MODE, bool RND, bool CVTA>
__global__ __launch_bounds__(128)
void gemm_tf32(const float* __restrict__ Ag, const float* __restrict__ Bg,
               float* __restrict__ Cg,
               int M, int N, int K, int lda, int ldb, int ldc,
               long long strideA, long long strideB, long long strideC,
               const float* __restrict__ bias,
               const int* __restrict__ mask, int maskStride, float invscale) {
    extern __shared__ uint32_t sh[];
    uint32_t* Asm = sh;                   // [2][BM][SA]
    uint32_t* Bsm = sh + 2 * BM * SA;     // [2][BN][SA]

    const int bz = blockIdx.z;
    const float* A = Ag + bz * strideA;
    const float* B = Bg + bz * strideB;
    float* C = Cg + bz * strideC;

    const int bm = blockIdx.y * BM;
    const int bn = blockIdx.x * BN;
    const int tid  = threadIdx.x;
    const int lane = tid & 31;
    const int warp = tid >> 5;
    const int wm = (warp & 1) * 64;
    const int wn = (warp >> 1) * 64;

    // loader: thread handles rows r0, r0+32, r0+64, r0+96 at k quad q4
    const int r0 = tid >> 2;
    const int q4 = (tid & 3) * 4;

    float4 ra[4], rb[4];
    auto gather = [&](int s) {
        const int k0 = s * BK;
#pragma unroll
        for (int i = 0; i < 4; i++)
            ra[i] = *reinterpret_cast<const float4*>(
                &A[(size_t)(bm + r0 + i * 32) * lda + k0 + q4]);
#pragma unroll
        for (int i = 0; i < 4; i++)
            rb[i] = *reinterpret_cast<const float4*>(
                &B[(size_t)(bn + r0 + i * 32) * ldb + k0 + q4]);
    };
    auto scatter = [&](int st) {
        uint32_t* Ad = Asm + st * BM * SA;
        uint32_t* Bd = Bsm + st * BN * SA;
#pragma unroll
        for (int i = 0; i < 4; i++) {
            uint4 u;
            if (CVTA) {
                u.x = f2tf32(ra[i].x); u.y = f2tf32(ra[i].y);
                u.z = f2tf32(ra[i].z); u.w = f2tf32(ra[i].w);
            } else {
                u.x = __float_as_uint(ra[i].x); u.y = __float_as_uint(ra[i].y);
                u.z = __float_as_uint(ra[i].z); u.w = __float_as_uint(ra[i].w);
            }
            *reinterpret_cast<uint4*>(&Ad[(r0 + i * 32) * SA + q4]) = u;
            uint4 v;
            v.x = __float_as_uint(rb[i].x); v.y = __float_as_uint(rb[i].y);
            v.z = __float_as_uint(rb[i].z); v.w = __float_as_uint(rb[i].w);
            *reinterpret_cast<uint4*>(&Bd[(r0 + i * 32) * SA + q4]) = v;
        }
    };

    float acc[4][8][4];
#pragma unroll
    for (int mt = 0; mt < 4; mt++)
#pragma unroll
        for (int nt = 0; nt < 8; nt++)
#pragma unroll
            for (int r = 0; r < 4; r++) acc[mt][nt][r] = 0.f;

    auto compute = [&](int st) {
        const uint32_t* A0 = Asm + st * BM * SA;
        const uint32_t* B0 = Bsm + st * BN * SA;
#pragma unroll
        for (int kg = 0; kg < 2; kg++) {
            const int kk = kg * 8 + (lane & 3);
            uint32_t a[4][4];
#pragma unroll
            for (int mt = 0; mt < 4; mt++) {
                const uint32_t* p = A0 + (wm + mt * 16 + (lane >> 2)) * SA + kk;
                a[mt][0] = p[0];
                a[mt][1] = p[8 * SA];
                a[mt][2] = p[4];
                a[mt][3] = p[8 * SA + 4];
            }
            uint32_t b[8][2];
#pragma unroll
            for (int nt = 0; nt < 8; nt++) {
                const uint32_t* p = B0 + (wn + nt * 8 + (lane >> 2)) * SA + kk;
                b[nt][0] = p[0];
                b[nt][1] = p[4];
            }
#pragma unroll
            for (int mt = 0; mt < 4; mt++)
#pragma unroll
                for (int nt = 0; nt < 8; nt++)
                    mma_tf32(acc[mt][nt], a[mt], b[nt]);
        }
    };

    gather(0);
    scatter(0);
    __syncthreads();

    const int NS = K / BK;
    for (int s = 0; s < NS; s++) {
        if (s + 1 < NS) gather(s + 1);
        compute(s & 1);
        if (s + 1 < NS) scatter((s + 1) & 1);
        __syncthreads();
    }

    // ---- epilogue ----
#pragma unroll
    for (int mt = 0; mt < 4; mt++) {
        const int row0 = bm + wm + mt * 16 + (lane >> 2);
#pragma unroll
        for (int nt = 0; nt < 8; nt++) {
            const int col = bn + wn + nt * 8 + (lane & 3) * 2;
#pragma unroll
            for (int half = 0; half < 2; half++) {
                const int row = row0 + half * 8;
                float v0 = acc[mt][nt][half * 2 + 0];
                float v1 = acc[mt][nt][half * 2 + 1];
                if (MODE == 1) {
                    v0 += bias[col];
                    v1 += bias[col + 1];
                } else if (MODE == 2) {
                    const int* mrow = mask + (size_t)bz * maskStride;
                    v0 = v0 * invscale + (float)mrow[col]     * -1e9f;
                    v1 = v1 * invscale + (float)mrow[col + 1] * -1e9f;
                }
                if (RND) { v0 = roundtf(v0); v1 = roundtf(v1); }
                float2 st; st.x = v0; st.y = v1;
                *reinterpret_cast<float2*>(&C[(size_t)row * ldc + col]) = st;
            }
        }
    }
}

// ---------------------------------------------------------------------------
// Row softmax over SK=1024. 256 threads, 4 elems/thread.
// Writes exact att to attOut (replicated H times) and tf32-rounded att to S
// (the AV GEMM's A operand).
// ---------------------------------------------------------------------------
__global__ __launch_bounds__(256)
void softmax_kernel(float* __restrict__ S, float* __restrict__ attOut,
                    int writeAtt) {
    const int q = blockIdx.x;
    const int b = blockIdx.y;
    const int tid = threadIdx.x;

    float* row = S + ((size_t)b * C_SQ + q) * C_SK;
    float4 x = *reinterpret_cast<const float4*>(&row[tid * 4]);

    __shared__ float red[256];
    float m = fmaxf(fmaxf(x.x, x.y), fmaxf(x.z, x.w));
    red[tid] = m;
    __syncthreads();
#pragma unroll
    for (int s = 128; s > 0; s >>= 1) {
        if (tid < s) red[tid] = fmaxf(red[tid], red[tid + s]);
        __syncthreads();
    }
    const float rowmax = red[0];
    __syncthreads();

    x.x = expf(x.x - rowmax);
    x.y = expf(x.y - rowmax);
    x.z = expf(x.z - rowmax);
    x.w = expf(x.w - rowmax);

    red[tid] = x.x + x.y + x.z + x.w;
    __syncthreads();
#pragma unroll
    for (int s = 128; s > 0; s >>= 1) {
        if (tid < s) red[tid] += red[tid + s];
        __syncthreads();
    }
    const float inv = 1.f / red[0];
    __syncthreads();

    x.x *= inv; x.y *= inv; x.z *= inv; x.w *= inv;

    if (writeAtt) {
        size_t base = ((size_t)b * C_H * C_SQ + q) * C_SK + tid * 4;
#pragma unroll
        for (int h = 0; h < C_H; h++)
            *reinterpret_cast<float4*>(&attOut[base + (size_t)h * C_SQ * C_SK]) = x;
    }

    // rounded copy for the AV GEMM
    float4 xr;
    xr.x = roundtf(x.x); xr.y = roundtf(x.y);
    xr.z = roundtf(x.z); xr.w = roundtf(x.w);
    *reinterpret_cast<float4*>(&row[tid * 4]) = xr;
}

// ---------------------------------------------------------------------------
// Launch
// ---------------------------------------------------------------------------
extern "C" void kernel_launch(void* const* d_in, const int* in_sizes, int n_in,
                              void* d_out, int out_size) {
    const float* Q    = (const float*)d_in[0];
    const float* K    = (const float*)d_in[1];
    const float* V    = (const float*)d_in[2];
    const int*   mask = (const int*)  d_in[3];
    const float* Wq   = (const float*)d_in[4];
    const float* bq   = (const float*)d_in[5];
    const float* Wk   = (const float*)d_in[6];
    const float* bk   = (const float*)d_in[7];
    const float* Wv   = (const float*)d_in[8];
    const float* bv   = (const float*)d_in[9];
    const float* Wl   = (const float*)d_in[10];
    const float* bl   = (const float*)d_in[11];

    float *pQl, *pKl, *pVl, *pVlT, *pS, *pHead, *pWeff, *pWqT, *pWkT, *pWvT, *pWeffT;
    cudaGetSymbolAddress((void**)&pQl,    g_Ql);
    cudaGetSymbolAddress((void**)&pKl,    g_Kl);
    cudaGetSymbolAddress((void**)&pVl,    g_Vl);
    cudaGetSymbolAddress((void**)&pVlT,   g_VlT);
    cudaGetSymbolAddress((void**)&pS,     g_S);
    cudaGetSymbolAddress((void**)&pHead,  g_head);
    cudaGetSymbolAddress((void**)&pWeff,  g_Weff);
    cudaGetSymbolAddress((void**)&pWqT,   g_WqT);
    cudaGetSymbolAddress((void**)&pWkT,   g_WkT);
    cudaGetSymbolAddress((void**)&pWvT,   g_WvT);
    cudaGetSymbolAddress((void**)&pWeffT, g_WeffT);

    float* Y = (float*)d_out;
    const long long ySize   = (long long)C_B * C_SQ * C_DM;
    const long long attSize = (long long)C_B * C_H * C_SQ * C_SK;
    const int writeAtt = ((long long)out_size >= ySize + attSize) ? 1 : 0;
    float* attOut = Y + ySize;

    const float invscale = 1.0f / sqrtf((float)C_DM);
    const dim3 blk(128);

    // Weff = sum over H of Wl blocks; transposes (+tf32 round for weights)
    wl_reduce_kernel<<<(C_DM * C_DM) / 256, 256>>>(Wl, pWeff);
    {
        dim3 tgrid(C_DM / 32, C_DM / 32, 1);
        dim3 tblk(32, 8);
        transpose_kernel<true><<<tgrid, tblk>>>(Wq,    pWqT,   C_DM, C_DM);
        transpose_kernel<true><<<tgrid, tblk>>>(Wk,    pWkT,   C_DM, C_DM);
        transpose_kernel<true><<<tgrid, tblk>>>(Wv,    pWvT,   C_DM, C_DM);
        transpose_kernel<true><<<tgrid, tblk>>>(pWeff, pWeffT, C_DM, C_DM);
    }

    // Projections: [8192,512] x [512,512]^T + bias, round result
    {
        dim3 grid(C_DM / BN, (C_B * C_SQ) / BM, 1);
        gemm_tf32<1, true, true><<<grid, blk, SMEM_BYTES>>>(Q, pWqT, pQl,
            C_B * C_SQ, C_DM, C_DM, C_DM, C_DM, C_DM, 0, 0, 0,
            bq, nullptr, 0, 0.f);
        gemm_tf32<1, true, true><<<grid, blk, SMEM_BYTES>>>(K, pWkT, pKl,
            C_B * C_SK, C_DM, C_DM, C_DM, C_DM, C_DM, 0, 0, 0,
            bk, nullptr, 0, 0.f);
        gemm_tf32<1, true, true><<<grid, blk, SMEM_BYTES>>>(V, pWvT, pVl,
            C_B * C_SK, C_DM, C_DM, C_DM, C_DM, C_DM, 0, 0, 0,
            bv, nullptr, 0, 0.f);
    }

    // Vl -> VlT per batch (already rounded)
    {
        dim3 tgrid(C_DM / 32, C_SK / 32, C_B);
        dim3 tblk(32, 8);
        transpose_kernel<false><<<tgrid, tblk>>>(pVl, pVlT, C_SK, C_DM);
    }

    // scores = Ql @ Kl^T * invscale + mask * (-1e9)  (exact fp32 out)
    {
        dim3 grid(C_SK / BN, C_SQ / BM, C_B);
        gemm_tf32<2, false, false><<<grid, blk, SMEM_BYTES>>>(pQl, pKl, pS,
            C_SQ, C_SK, C_DM, C_DM, C_DM, C_SK,
            (long long)C_SQ * C_DM, (long long)C_SK * C_DM,
            (long long)C_SQ * C_SK,
            nullptr, mask, C_SK, invscale);
    }

    // softmax: exact -> att_ws, rounded -> S
    {
        dim3 grid(C_SQ, C_B);
        softmax_kernel<<<grid, 256>>>(pS, attOut, writeAtt);
    }

    // head = att @ Vl (B = VlT [DM, SK]), round result
    {
        dim3 grid(C_DM / BN, C_SQ / BM, C_B);
        gemm_tf32<0, true, false><<<grid, blk, SMEM_BYTES>>>(pS, pVlT, pHead,
            C_SQ, C_DM, C_SK, C_SK, C_SK, C_DM,
            (long long)C_SQ * C_SK, (long long)C_SK * C_DM,
            (long long)C_SQ * C_DM,
            nullptr, nullptr, 0, 0.f);
    }

    // Y = head @ Weff + bl (exact fp32 out)
    {
        dim3 grid(C_DM / BN, (C_B * C_SQ) / BM, 1);
        gemm_tf32<1, false, false><<<grid, blk, SMEM_BYTES>>>(pHead, pWeffT, Y,
            C_B * C_SQ, C_DM, C_DM, C_DM, C_DM, C_DM, 0, 0, 0,
            bl, nullptr, 0, 0.f);
    }
}

// round 5
// speedup vs baseline: 2.6981x; 1.0065x over previous
#include <cuda_runtime.h>
#include <math.h>
#include <stdint.h>

// Problem constants
constexpr int C_DM = 512;
constexpr int C_H  = 8;
constexpr int C_B  = 8;
constexpr int C_SQ = 1024;
constexpr int C_SK = 1024;

// GEMM tiling: CTA 128x256x16, 8 warps (2x4), warp tile 64x64, 3-stage cp.async
constexpr int BM = 128;
constexpr int BN = 256;
constexpr int BK = 16;
constexpr int SA = 20;                      // smem row stride in words (16 data + 4 pad)
constexpr int STAGES = 3;
constexpr int A_WORDS = BM * SA;            // 2560
constexpr int B_WORDS = BN * SA;            // 5120
constexpr int STAGE_WORDS = A_WORDS + B_WORDS;       // 7680
constexpr int SMEM_BYTES = STAGES * STAGE_WORDS * 4; // 92160

// Scratch (allocation-free rule: __device__ globals)
__device__ float g_Qr [C_B * C_SQ * C_DM];
__device__ float g_Kr [C_B * C_SK * C_DM];
__device__ float g_Vr [C_B * C_SK * C_DM];
__device__ float g_Ql [C_B * C_SQ * C_DM];
__device__ float g_Kl [C_B * C_SK * C_DM];
__device__ float g_Vl [C_B * C_SK * C_DM];
__device__ float g_VlT[C_B * C_SK * C_DM];
__device__ float g_S  [C_B * (size_t)C_SQ * C_SK];
__device__ float g_head[C_B * C_SQ * C_DM];
__device__ float g_Weff [C_DM * C_DM];
__device__ float g_WqT  [C_DM * C_DM];
__device__ float g_WkT  [C_DM * C_DM];
__device__ float g_WvT  [C_DM * C_DM];
__device__ float g_WeffT[C_DM * C_DM];

__device__ __forceinline__ uint32_t f2tf32(float f) {
    uint32_t u;
    asm("cvt.rna.tf32.f32 %0, %1;" : "=r"(u) : "f"(f));
    return u;
}
__device__ __forceinline__ float roundtf(float f) {
    return __uint_as_float(f2tf32(f));
}

__device__ __forceinline__ uint32_t smem_u32(const void* p) {
    uint32_t a;
    asm("{ .reg .u64 t; cvta.to.shared.u64 t, %1; cvt.u32.u64 %0, t; }"
        : "=r"(a) : "l"(p));
    return a;
}

__device__ __forceinline__ void cp_async16(uint32_t dst, const void* src) {
    asm volatile("cp.async.cg.shared.global [%0], [%1], 16;"
                 :: "r"(dst), "l"(src));
}
#define CP_COMMIT() asm volatile("cp.async.commit_group;" ::: "memory")
#define CP_WAIT1()  asm volatile("cp.async.wait_group 1;"  ::: "memory")

__device__ __forceinline__ void mma_tf32(float c[4],
                                         const uint32_t a[4],
                                         const uint32_t b[2]) {
    asm volatile(
        "mma.sync.aligned.m16n8k8.row.col.f32.tf32.tf32.f32 "
        "{%0,%1,%2,%3}, {%4,%5,%6,%7}, {%8,%9}, {%0,%1,%2,%3};"
        : "+f"(c[0]), "+f"(c[1]), "+f"(c[2]), "+f"(c[3])
        : "r"(a[0]), "r"(a[1]), "r"(a[2]), "r"(a[3]),
          "r"(b[0]), "r"(b[1]));
}

// ---------------------------------------------------------------------------
// Elementwise tf32 round (vectorized)
// ---------------------------------------------------------------------------
__global__ __launch_bounds__(256)
void round_copy_kernel(const float4* __restrict__ in, float4* __restrict__ out,
                       int n4) {
    int i = blockIdx.x * blockDim.x + threadIdx.x;
    if (i < n4) {
        float4 v = in[i];
        v.x = roundtf(v.x); v.y = roundtf(v.y);
        v.z = roundtf(v.z); v.w = roundtf(v.w);
        out[i] = v;
    }
}

// ---------------------------------------------------------------------------
// Wl reduction: Weff[d, j] = sum_h Wl[h*DM + d, j]
// ---------------------------------------------------------------------------
__global__ void wl_reduce_kernel(const float* __restrict__ Wl,
                                 float* __restrict__ Weff) {
    int idx = blockIdx.x * blockDim.x + threadIdx.x;
    int d = idx / C_DM;
    int j = idx % C_DM;
    float s = 0.f;
#pragma unroll
    for (int h = 0; h < C_H; h++)
        s += Wl[((size_t)(h * C_DM + d)) * C_DM + j];
    Weff[idx] = s;
}

// ---------------------------------------------------------------------------
// Tiled transpose, batched over z. RND: round output to tf32.
// ---------------------------------------------------------------------------
template <bool RND>
__global__ __launch_bounds__(256)
void transpose_kernel(const float* __restrict__ in, float* __restrict__ out,
                      int R, int C) {
    __shared__ float t[32][33];
    const size_t zoff = (size_t)blockIdx.z * R * C;
    in  += zoff;
    out += zoff;
    int c = blockIdx.x * 32 + threadIdx.x;
    int r = blockIdx.y * 32 + threadIdx.y;
#pragma unroll
    for (int i = 0; i < 4; i++)
        t[threadIdx.y + i * 8][threadIdx.x] = in[(size_t)(r + i * 8) * C + c];
    __syncthreads();
    int co = blockIdx.y * 32 + threadIdx.x;
    int ro = blockIdx.x * 32 + threadIdx.y;
#pragma unroll
    for (int i = 0; i < 4; i++) {
        float v = t[threadIdx.x][threadIdx.y + i * 8];
        if (RND) v = roundtf(v);
        out[(size_t)(ro + i * 8) * R + co] = v;
    }
}

// ---------------------------------------------------------------------------
// TF32 tensor-core GEMM: C[M,N] = A[M,K] * B[N,K]^T, batched (z).
// A and B must be tf32-pre-rounded in gmem.
//   MODE 0: C = acc ; MODE 1: C = acc + bias[col]
//   MODE 2: C = acc*invscale + (float)mask[bz*maskStride + col] * (-1e9)
//   RND : round result to tf32 (when it feeds a later GEMM)
// M%128==0, N%256==0, K%32==0. 256 threads, 8 warps (2x4) of 64x64.
// ---------------------------------------------------------------------------
template <int MODE, bool RND>
__global__ __launch_bounds__(256)
void gemm_tf32(const float* __restrict__ Ag, const float* __restrict__ Bg,
               float* __restrict__ Cg,
               int M, int N, int K, int lda, int ldb, int ldc,
               long long strideA, long long strideB, long long strideC,
               const float* __restrict__ bias,
               const int* __restrict__ mask, int maskStride, float invscale) {
    extern __shared__ uint32_t sh[];
    const uint32_t smem_base = smem_u32(sh);

    const int bz = blockIdx.z;
    const float* A = Ag + bz * strideA;
    const float* B = Bg + bz * strideB;
    float* C = Cg + bz * strideC;

    const int bm = blockIdx.y * BM;
    const int bn = blockIdx.x * BN;
    const int tid  = threadIdx.x;
    const int lane = tid & 31;
    const int warp = tid >> 5;
    const int wm = (warp & 1) * 64;
    const int wn = (warp >> 1) * 64;

    // cp.async producer: A = 512 16B-chunks (2/thread), B = 1024 (4/thread)
    auto issue = [&](int s) {
        const int st = s % STAGES;
        const uint32_t sa = smem_base + st * STAGE_WORDS * 4;
        const uint32_t sb = sa + A_WORDS * 4;
        const int k0 = s * BK;
#pragma unroll
        for (int i = 0; i < 2; i++) {
            const int c = tid + i * 256;
            const int row = c >> 2, kc = (c & 3) * 4;
            cp_async16(sa + (row * SA + kc) * 4,
                       A + (size_t)(bm + row) * lda + k0 + kc);
        }
#pragma unroll
        for (int i = 0; i < 4; i++) {
            const int c = tid + i * 256;
            const int row = c >> 2, kc = (c & 3) * 4;
            cp_async16(sb + (row * SA + kc) * 4,
                       B + (size_t)(bn + row) * ldb + k0 + kc);
        }
    };

    float acc[4][8][4];
#pragma unroll
    for (int mt = 0; mt < 4; mt++)
#pragma unroll
        for (int nt = 0; nt < 8; nt++)
#pragma unroll
            for (int r = 0; r < 4; r++) acc[mt][nt][r] = 0.f;

    auto compute = [&](int st) {
        const uint32_t* A0 = sh + st * STAGE_WORDS;
        const uint32_t* B0 = A0 + A_WORDS;
#pragma unroll
        for (int kg = 0; kg < 2; kg++) {
            const int kk = kg * 8 + (lane & 3);
            uint32_t a[4][4];
#pragma unroll
            for (int mt = 0; mt < 4; mt++) {
                const uint32_t* p = A0 + (wm + mt * 16 + (lane >> 2)) * SA + kk;
                a[mt][0] = p[0];
                a[mt][1] = p[8 * SA];
                a[mt][2] = p[4];
                a[mt][3] = p[8 * SA + 4];
            }
            uint32_t b[8][2];
#pragma unroll
            for (int nt = 0; nt < 8; nt++) {
                const uint32_t* p = B0 + (wn + nt * 8 + (lane >> 2)) * SA + kk;
                b[nt][0] = p[0];
                b[nt][1] = p[4];
            }
#pragma unroll
            for (int mt = 0; mt < 4; mt++)
#pragma unroll
                for (int nt = 0; nt < 8; nt++)
                    mma_tf32(acc[mt][nt], a[mt], b[nt]);
        }
    };

    const int NS = K / BK;
    issue(0); CP_COMMIT();
    issue(1); CP_COMMIT();

    for (int s = 0; s < NS; s++) {
        CP_WAIT1();
        __syncthreads();
        if (s + 2 < NS) issue(s + 2);
        CP_COMMIT();
        compute(s % STAGES);
    }

    // ---- epilogue ----
#pragma unroll
    for (int mt = 0; mt < 4; mt++) {
        const int row0 = bm + wm + mt * 16 + (lane >> 2);
#pragma unroll
        for (int nt = 0; nt < 8; nt++) {
            const int col = bn + wn + nt * 8 + (lane & 3) * 2;
#pragma unroll
            for (int half = 0; half < 2; half++) {
                const int row = row0 + half * 8;
                float v0 = acc[mt][nt][half * 2 + 0];
                float v1 = acc[mt][nt][half * 2 + 1];
                if (MODE == 1) {
                    v0 += bias[col];
                    v1 += bias[col + 1];
                } else if (MODE == 2) {
                    const int* mrow = mask + (size_t)bz * maskStride;
                    v0 = v0 * invscale + (float)mrow[col]     * -1e9f;
                    v1 = v1 * invscale + (float)mrow[col + 1] * -1e9f;
                }
                if (RND) { v0 = roundtf(v0); v1 = roundtf(v1); }
                float2 st; st.x = v0; st.y = v1;
                *reinterpret_cast<float2*>(&C[(size_t)row * ldc + col]) = st;
            }
        }
    }
}

// ---------------------------------------------------------------------------
// Row softmax over SK=1024. 256 threads, 4 elems/thread.
// Exact att -> attOut (replicated H times, streaming stores);
// tf32-rounded att -> S (AV GEMM's A operand).
// ---------------------------------------------------------------------------
__global__ __launch_bounds__(256)
void softmax_kernel(float* __restrict__ S, float* __restrict__ attOut,
                    int writeAtt) {
    const int q = blockIdx.x;
    const int b = blockIdx.y;
    const int tid = threadIdx.x;

    float* row = S + ((size_t)b * C_SQ + q) * C_SK;
    float4 x = *reinterpret_cast<const float4*>(&row[tid * 4]);

    __shared__ float red[256];
    float m = fmaxf(fmaxf(x.x, x.y), fmaxf(x.z, x.w));
    red[tid] = m;
    __syncthreads();
#pragma unroll
    for (int s = 128; s > 0; s >>= 1) {
        if (tid < s) red[tid] = fmaxf(red[tid], red[tid + s]);
        __syncthreads();
    }
    const float rowmax = red[0];
    __syncthreads();

    x.x = expf(x.x - rowmax);
    x.y = expf(x.y - rowmax);
    x.z = expf(x.z - rowmax);
    x.w = expf(x.w - rowmax);

    red[tid] = x.x + x.y + x.z + x.w;
    __syncthreads();
#pragma unroll
    for (int s = 128; s > 0; s >>= 1) {
        if (tid < s) red[tid] += red[tid + s];
        __syncthreads();
    }
    const float inv = 1.f / red[0];
    __syncthreads();

    x.x *= inv; x.y *= inv; x.z *= inv; x.w *= inv;

    if (writeAtt) {
        size_t base = ((size_t)b * C_H * C_SQ + q) * C_SK + tid * 4;
#pragma unroll
        for (int h = 0; h < C_H; h++)
            __stcs(reinterpret_cast<float4*>(&attOut[base + (size_t)h * C_SQ * C_SK]), x);
    }

    float4 xr;
    xr.x = roundtf(x.x); xr.y = roundtf(x.y);
    xr.z = roundtf(x.z); xr.w = roundtf(x.w);
    *reinterpret_cast<float4*>(&row[tid * 4]) = xr;
}

// ---------------------------------------------------------------------------
// Launch
// ---------------------------------------------------------------------------
extern "C" void kernel_launch(void* const* d_in, const int* in_sizes, int n_in,
                              void* d_out, int out_size) {
    const float* Q    = (const float*)d_in[0];
    const float* K    = (const float*)d_in[1];
    const float* V    = (const float*)d_in[2];
    const int*   mask = (const int*)  d_in[3];
    const float* Wq   = (const float*)d_in[4];
    const float* bq   = (const float*)d_in[5];
    const float* Wk   = (const float*)d_in[6];
    const float* bk   = (const float*)d_in[7];
    const float* Wv   = (const float*)d_in[8];
    const float* bv   = (const float*)d_in[9];
    const float* Wl   = (const float*)d_in[10];
    const float* bl   = (const float*)d_in[11];

    float *pQr, *pKr, *pVr, *pQl, *pKl, *pVl, *pVlT, *pS, *pHead;
    float *pWeff, *pWqT, *pWkT, *pWvT, *pWeffT;
    cudaGetSymbolAddress((void**)&pQr,    g_Qr);
    cudaGetSymbolAddress((void**)&pKr,    g_Kr);
    cudaGetSymbolAddress((void**)&pVr,    g_Vr);
    cudaGetSymbolAddress((void**)&pQl,    g_Ql);
    cudaGetSymbolAddress((void**)&pKl,    g_Kl);
    cudaGetSymbolAddress((void**)&pVl,    g_Vl);
    cudaGetSymbolAddress((void**)&pVlT,   g_VlT);
    cudaGetSymbolAddress((void**)&pS,     g_S);
    cudaGetSymbolAddress((void**)&pHead,  g_head);
    cudaGetSymbolAddress((void**)&pWeff,  g_Weff);
    cudaGetSymbolAddress((void**)&pWqT,   g_WqT);
    cudaGetSymbolAddress((void**)&pWkT,   g_WkT);
    cudaGetSymbolAddress((void**)&pWvT,   g_WvT);
    cudaGetSymbolAddress((void**)&pWeffT, g_WeffT);

    float* Y = (float*)d_out;
    const long long ySize   = (long long)C_B * C_SQ * C_DM;
    const long long attSize = (long long)C_B * C_H * C_SQ * C_SK;
    const int writeAtt = ((long long)out_size >= ySize + attSize) ? 1 : 0;
    float* attOut = Y + ySize;

    const float invscale = 1.0f / sqrtf((float)C_DM);
    const dim3 blk(256);

    cudaFuncSetAttribute(gemm_tf32<0, true>,  cudaFuncAttributeMaxDynamicSharedMemorySize, SMEM_BYTES);
    cudaFuncSetAttribute(gemm_tf32<1, true>,  cudaFuncAttributeMaxDynamicSharedMemorySize, SMEM_BYTES);
    cudaFuncSetAttribute(gemm_tf32<1, false>, cudaFuncAttributeMaxDynamicSharedMemorySize, SMEM_BYTES);
    cudaFuncSetAttribute(gemm_tf32<2, false>, cudaFuncAttributeMaxDynamicSharedMemorySize, SMEM_BYTES);

    // Pre-round inputs + weights (weights also transposed)
    {
        const int n4 = C_B * C_SQ * C_DM / 4;
        round_copy_kernel<<<n4 / 256, 256>>>((const float4*)Q, (float4*)pQr, n4);
        round_copy_kernel<<<n4 / 256, 256>>>((const float4*)K, (float4*)pKr, n4);
        round_copy_kernel<<<n4 / 256, 256>>>((const float4*)V, (float4*)pVr, n4);
    }
    wl_reduce_kernel<<<(C_DM * C_DM) / 256, 256>>>(Wl, pWeff);
    {
        dim3 tgrid(C_DM / 32, C_DM / 32, 1);
        dim3 tblk(32, 8);
        transpose_kernel<true><<<tgrid, tblk>>>(Wq,    pWqT,   C_DM, C_DM);
        transpose_kernel<true><<<tgrid, tblk>>>(Wk,    pWkT,   C_DM, C_DM);
        transpose_kernel<true><<<tgrid, tblk>>>(Wv,    pWvT,   C_DM, C_DM);
        transpose_kernel<true><<<tgrid, tblk>>>(pWeff, pWeffT, C_DM, C_DM);
    }

    // Projections: [8192,512] x [512,512]^T + bias, round result
    {
        dim3 grid(C_DM / BN, (C_B * C_SQ) / BM, 1);
        gemm_tf32<1, true><<<grid, blk, SMEM_BYTES>>>(pQr, pWqT, pQl,
            C_B * C_SQ, C_DM, C_DM, C_DM, C_DM, C_DM, 0, 0, 0,
            bq, nullptr, 0, 0.f);
        gemm_tf32<1, true><<<grid, blk, SMEM_BYTES>>>(pKr, pWkT, pKl,
            C_B * C_SK, C_DM, C_DM, C_DM, C_DM, C_DM, 0, 0, 0,
            bk, nullptr, 0, 0.f);
        gemm_tf32<1, true><<<grid, blk, SMEM_BYTES>>>(pVr, pWvT, pVl,
            C_B * C_SK, C_DM, C_DM, C_DM, C_DM, C_DM, 0, 0, 0,
            bv, nullptr, 0, 0.f);
    }

    // Vl -> VlT per batch (already rounded)
    {
        dim3 tgrid(C_DM / 32, C_SK / 32, C_B);
        dim3 tblk(32, 8);
        transpose_kernel<false><<<tgrid, tblk>>>(pVl, pVlT, C_SK, C_DM);
    }

    // scores = Ql @ Kl^T * invscale + mask * (-1e9)  (exact fp32 out)
    {
        dim3 grid(C_SK / BN, C_SQ / BM, C_B);
        gemm_tf32<2, false><<<grid, blk, SMEM_BYTES>>>(pQl, pKl, pS,
            C_SQ, C_SK, C_DM, C_DM, C_DM, C_SK,
            (long long)C_SQ * C_DM, (long long)C_SK * C_DM,
            (long long)C_SQ * C_SK,
            nullptr, mask, C_SK, invscale);
    }

    // softmax: exact -> att_ws, rounded -> S
    {
        dim3 grid(C_SQ, C_B);
        softmax_kernel<<<grid, 256>>>(pS, attOut, writeAtt);
    }

    // head = att @ Vl (B = VlT [DM, SK]), round result
    {
        dim3 grid(C_DM / BN, C_SQ / BM, C_B);
        gemm_tf32<0, true><<<grid, blk, SMEM_BYTES>>>(pS, pVlT, pHead,
            C_SQ, C_DM, C_SK, C_SK, C_SK, C_DM,
            (long long)C_SQ * C_SK, (long long)C_SK * C_DM,
            (long long)C_SQ * C_DM,
            nullptr, nullptr, 0, 0.f);
    }

    // Y = head @ Weff + bl (exact fp32 out)
    {
        dim3 grid(C_DM / BN, (C_B * C_SQ) / BM, 1);
        gemm_tf32<1, false><<<grid, blk, SMEM_BYTES>>>(pHead, pWeffT, Y,
            C_B * C_SQ, C_DM, C_DM, C_DM, C_DM, C_DM, 0, 0, 0,
            bl, nullptr, 0, 0.f);
    }
}

// round 8
// speedup vs baseline: 3.1023x; 1.1498x over previous
#include <cuda_runtime.h>
#include <math.h>
#include <stdint.h>

// Problem constants
constexpr int C_DM = 512;
constexpr int C_H  = 8;
constexpr int C_B  = 8;
constexpr int C_SQ = 1024;
constexpr int C_SK = 1024;

// GEMM tiling: CTA 128x256x16, 8 warps (2x4), warp tile 64x64, 4-stage cp.async
constexpr int BM = 128;
constexpr int BN = 256;
constexpr int BK = 16;
constexpr int SA  = 20;    // smem row stride (words) for [row][k] tiles (A, and B when TB)
constexpr int SBF = 264;   // smem row stride (words) for [k][n] B tiles (TB=false)
constexpr int STAGES = 4;
constexpr int A_WORDS = BM * SA;                       // 2560
constexpr int B_WORDS_T = BN * SA;                     // 5120
constexpr int B_WORDS_F = BK * SBF;                    // 4224

// Scratch (allocation-free rule: __device__ globals)
__device__ float g_Ql [C_B * C_SQ * C_DM];
__device__ float g_Kl [C_B * C_SK * C_DM];
__device__ float g_Vl [C_B * C_SK * C_DM];
__device__ float g_S  [C_B * (size_t)C_SQ * C_SK];
__device__ float g_head[C_B * C_SQ * C_DM];
__device__ float g_Weff[C_DM * C_DM];
__device__ float g_WqR [C_DM * C_DM];
__device__ float g_WkR [C_DM * C_DM];
__device__ float g_WvR [C_DM * C_DM];

__device__ __forceinline__ uint32_t f2tf32(float f) {
    uint32_t u;
    asm("cvt.rna.tf32.f32 %0, %1;" : "=r"(u) : "f"(f));
    return u;
}
__device__ __forceinline__ float roundtf(float f) {
    return __uint_as_float(f2tf32(f));
}

__device__ __forceinline__ uint32_t smem_u32(const void* p) {
    uint32_t a;
    asm("{ .reg .u64 t; cvta.to.shared.u64 t, %1; cvt.u32.u64 %0, t; }"
        : "=r"(a) : "l"(p));
    return a;
}

__device__ __forceinline__ void cp_async16(uint32_t dst, const void* src) {
    asm volatile("cp.async.cg.shared.global [%0], [%1], 16;"
                 :: "r"(dst), "l"(src));
}
#define CP_COMMIT() asm volatile("cp.async.commit_group;" ::: "memory")
#define CP_WAIT2()  asm volatile("cp.async.wait_group 2;"  ::: "memory")

__device__ __forceinline__ void mma_tf32(float c[4],
                                         const uint32_t a[4],
                                         const uint32_t b[2]) {
    asm volatile(
        "mma.sync.aligned.m16n8k8.row.col.f32.tf32.tf32.f32 "
        "{%0,%1,%2,%3}, {%4,%5,%6,%7}, {%8,%9}, {%0,%1,%2,%3};"
        : "+f"(c[0]), "+f"(c[1]), "+f"(c[2]), "+f"(c[3])
        : "r"(a[0]), "r"(a[1]), "r"(a[2]), "r"(a[3]),
          "r"(b[0]), "r"(b[1]));
}

// ---------------------------------------------------------------------------
// Elementwise tf32 round (vectorized) — only used on 1MB weight matrices
// ---------------------------------------------------------------------------
__global__ __launch_bounds__(256)
void round_copy_kernel(const float4* __restrict__ in, float4* __restrict__ out,
                       int n4) {
    int i = blockIdx.x * blockDim.x + threadIdx.x;
    if (i < n4) {
        float4 v = in[i];
        v.x = roundtf(v.x); v.y = roundtf(v.y);
        v.z = roundtf(v.z); v.w = roundtf(v.w);
        out[i] = v;
    }
}

// ---------------------------------------------------------------------------
// Wl reduction: Weff[d, j] = sum_h Wl[h*DM + d, j], tf32-rounded.
// ---------------------------------------------------------------------------
__global__ void wl_reduce_kernel(const float* __restrict__ Wl,
                                 float* __restrict__ Weff) {
    int idx = blockIdx.x * blockDim.x + threadIdx.x;
    int d = idx / C_DM;
    int j = idx % C_DM;
    float s = 0.f;
#pragma unroll
    for (int h = 0; h < C_H; h++)
        s += Wl[((size_t)(h * C_DM + d)) * C_DM + j];
    Weff[idx] = roundtf(s);
}

// ---------------------------------------------------------------------------
// TF32 tensor-core GEMM, batched (z):
//   TB=true : C[M,N] = A[M,K] * B[N,K]^T   (B row-major [N,K])
//   TB=false: C[M,N] = A[M,K] * B[K,N]     (B row-major [K,N])
//   MODE 0: C = acc ; MODE 1: C = acc + bias[col]
//   MODE 2: C = acc*invscale + (float)mask[bz*maskStride + col] * (-1e9)
//   RND : round result to tf32 (when it feeds a later GEMM)
// Operands may be raw fp32 (HW truncates to tf32).
// M%128==0, N%256==0, K%16==0. 256 threads, 8 warps (2x4) of 64x64.
// ---------------------------------------------------------------------------
template <int MODE, bool RND, bool TB>
__global__ __launch_bounds__(256)
void gemm_tf32(const float* __restrict__ Ag, const float* __restrict__ Bg,
               float* __restrict__ Cg,
               int M, int N, int K, int lda, int ldb, int ldc,
               long long strideA, long long strideB, long long strideC,
               const float* __restrict__ bias,
               const int* __restrict__ mask, int maskStride, float invscale) {
    constexpr int B_WORDS = TB ? B_WORDS_T : B_WORDS_F;
    constexpr int STAGE_WORDS = A_WORDS + B_WORDS;

    extern __shared__ uint32_t sh[];
    const uint32_t smem_base = smem_u32(sh);

    const int bz = blockIdx.z;
    const float* A = Ag + bz * strideA;
    const float* B = Bg + bz * strideB;
    float* C = Cg + bz * strideC;

    const int bm = blockIdx.y * BM;
    const int bn = blockIdx.x * BN;
    const int tid  = threadIdx.x;
    const int lane = tid & 31;
    const int warp = tid >> 5;
    const int wm = (warp & 1) * 64;
    const int wn = (warp >> 1) * 64;

    auto issue = [&](int s) {
        const int st = s % STAGES;
        const uint32_t sa = smem_base + st * STAGE_WORDS * 4;
        const uint32_t sb = sa + A_WORDS * 4;
        const int k0 = s * BK;
        // A: 128 rows x 4 16B-chunks = 512, 2/thread
#pragma unroll
        for (int i = 0; i < 2; i++) {
            const int c = tid + i * 256;
            const int row = c >> 2, kc = (c & 3) * 4;
            cp_async16(sa + (row * SA + kc) * 4,
                       A + (size_t)(bm + row) * lda + k0 + kc);
        }
        if (TB) {
            // B [N,K]: 256 rows x 4 chunks = 1024, 4/thread -> smem [n][k] SA
#pragma unroll
            for (int i = 0; i < 4; i++) {
                const int c = tid + i * 256;
                const int row = c >> 2, kc = (c & 3) * 4;
                cp_async16(sb + (row * SA + kc) * 4,
                           B + (size_t)(bn + row) * ldb + k0 + kc);
            }
        } else {
            // B [K,N]: 16 rows x 64 chunks = 1024, 4/thread -> smem [k][n] SBF
#pragma unroll
            for (int i = 0; i < 4; i++) {
                const int c = tid + i * 256;
                const int row = c >> 6, nc = (c & 63) * 4;
                cp_async16(sb + (row * SBF + nc) * 4,
                           B + (size_t)(k0 + row) * ldb + bn + nc);
            }
        }
    };

    float acc[4][8][4];
#pragma unroll
    for (int mt = 0; mt < 4; mt++)
#pragma unroll
        for (int nt = 0; nt < 8; nt++)
#pragma unroll
            for (int r = 0; r < 4; r++) acc[mt][nt][r] = 0.f;

    auto compute = [&](int st) {
        const uint32_t* A0 = sh + st * STAGE_WORDS;
        const uint32_t* B0 = A0 + A_WORDS;
#pragma unroll
        for (int kg = 0; kg < 2; kg++) {
            const int kk = kg * 8 + (lane & 3);
            uint32_t a[4][4];
#pragma unroll
            for (int mt = 0; mt < 4; mt++) {
                const uint32_t* p = A0 + (wm + mt * 16 + (lane >> 2)) * SA + kk;
                a[mt][0] = p[0];
                a[mt][1] = p[8 * SA];
                a[mt][2] = p[4];
                a[mt][3] = p[8 * SA + 4];
            }
            uint32_t b[8][2];
#pragma unroll
            for (int nt = 0; nt < 8; nt++) {
                if (TB) {
                    const uint32_t* p = B0 + (wn + nt * 8 + (lane >> 2)) * SA + kk;
                    b[nt][0] = p[0];
                    b[nt][1] = p[4];
                } else {
                    const uint32_t* p = B0 + kk * SBF + wn + nt * 8 + (lane >> 2);
                    b[nt][0] = p[0];
                    b[nt][1] = p[4 * SBF];
                }
            }
#pragma unroll
            for (int mt = 0; mt < 4; mt++)
#pragma unroll
                for (int nt = 0; nt < 8; nt++)
                    mma_tf32(acc[mt][nt], a[mt], b[nt]);
        }
    };

    const int NS = K / BK;
    issue(0); CP_COMMIT();
    issue(1); CP_COMMIT();
    issue(2); CP_COMMIT();

    for (int s = 0; s < NS; s++) {
        CP_WAIT2();
        __syncthreads();
        if (s + 3 < NS) issue(s + 3);
        CP_COMMIT();
        compute(s % STAGES);
    }

    // ---- epilogue ----
#pragma unroll
    for (int mt = 0; mt < 4; mt++) {
        const int row0 = bm + wm + mt * 16 + (lane >> 2);
#pragma unroll
        for (int nt = 0; nt < 8; nt++) {
            const int col = bn + wn + nt * 8 + (lane & 3) * 2;
#pragma unroll
            for (int half = 0; half < 2; half++) {
                const int row = row0 + half * 8;
                float v0 = acc[mt][nt][half * 2 + 0];
                float v1 = acc[mt][nt][half * 2 + 1];
                if (MODE == 1) {
                    v0 += bias[col];
                    v1 += bias[col + 1];
                } else if (MODE == 2) {
                    const int* mrow = mask + (size_t)bz * maskStride;
                    v0 = v0 * invscale + (float)mrow[col]     * -1e9f;
                    v1 = v1 * invscale + (float)mrow[col + 1] * -1e9f;
                }
                if (RND) { v0 = roundtf(v0); v1 = roundtf(v1); }
                float2 st; st.x = v0; st.y = v1;
                *reinterpret_cast<float2*>(&C[(size_t)row * ldc + col]) = st;
            }
        }
    }
}

// ---------------------------------------------------------------------------
// Row softmax over SK=1024. 256 threads, 4 elems/thread.
// Exact att -> attOut (replicated H times, streaming stores);
// tf32-rounded att -> S (AV GEMM's A operand).
// ---------------------------------------------------------------------------
__global__ __launch_bounds__(256)
void softmax_kernel(float* __restrict__ S, float* __restrict__ attOut,
                    int writeAtt) {
    const int q = blockIdx.x;
    const int b = blockIdx.y;
    const int tid = threadIdx.x;

    float* row = S + ((size_t)b * C_SQ + q) * C_SK;
    float4 x = *reinterpret_cast<const float4*>(&row[tid * 4]);

    __shared__ float red[256];
    float m = fmaxf(fmaxf(x.x, x.y), fmaxf(x.z, x.w));
    red[tid] = m;
    __syncthreads();
#pragma unroll
    for (int s = 128; s > 0; s >>= 1) {
        if (tid < s) red[tid] = fmaxf(red[tid], red[tid + s]);
        __syncthreads();
    }
    const float rowmax = red[0];
    __syncthreads();

    x.x = expf(x.x - rowmax);
    x.y = expf(x.y - rowmax);
    x.z = expf(x.z - rowmax);
    x.w = expf(x.w - rowmax);

    red[tid] = x.x + x.y + x.z + x.w;
    __syncthreads();
#pragma unroll
    for (int s = 128; s > 0; s >>= 1) {
        if (tid < s) red[tid] += red[tid + s];
        __syncthreads();
    }
    const float inv = 1.f / red[0];
    __syncthreads();

    x.x *= inv; x.y *= inv; x.z *= inv; x.w *= inv;

    if (writeAtt) {
        size_t base = ((size_t)b * C_H * C_SQ + q) * C_SK + tid * 4;
#pragma unroll
        for (int h = 0; h < C_H; h++)
            __stcs(reinterpret_cast<float4*>(&attOut[base + (size_t)h * C_SQ * C_SK]), x);
    }

    float4 xr;
    xr.x = roundtf(x.x); xr.y = roundtf(x.y);
    xr.z = roundtf(x.z); xr.w = roundtf(x.w);
    *reinterpret_cast<float4*>(&row[tid * 4]) = xr;
}

// ---------------------------------------------------------------------------
// Launch
// ---------------------------------------------------------------------------
extern "C" void kernel_launch(void* const* d_in, const int* in_sizes, int n_in,
                              void* d_out, int out_size) {
    const float* Q    = (const float*)d_in[0];
    const float* K    = (const float*)d_in[1];
    const float* V    = (const float*)d_in[2];
    const int*   mask = (const int*)  d_in[3];
    const float* Wq   = (const float*)d_in[4];
    const float* bq   = (const float*)d_in[5];
    const float* Wk   = (const float*)d_in[6];
    const float* bk   = (const float*)d_in[7];
    const float* Wv   = (const float*)d_in[8];
    const float* bv   = (const float*)d_in[9];
    const float* Wl   = (const float*)d_in[10];
    const float* bl   = (const float*)d_in[11];

    float *pQl, *pKl, *pVl, *pS, *pHead, *pWeff, *pWqR, *pWkR, *pWvR;
    cudaGetSymbolAddress((void**)&pQl,   g_Ql);
    cudaGetSymbolAddress((void**)&pKl,   g_Kl);
    cudaGetSymbolAddress((void**)&pVl,   g_Vl);
    cudaGetSymbolAddress((void**)&pS,    g_S);
    cudaGetSymbolAddress((void**)&pHead, g_head);
    cudaGetSymbolAddress((void**)&pWeff, g_Weff);
    cudaGetSymbolAddress((void**)&pWqR,  g_WqR);
    cudaGetSymbolAddress((void**)&pWkR,  g_WkR);
    cudaGetSymbolAddress((void**)&pWvR,  g_WvR);

    float* Y = (float*)d_out;
    const long long ySize   = (long long)C_B * C_SQ * C_DM;
    const long long attSize = (long long)C_B * C_H * C_SQ * C_SK;
    const int writeAtt = ((long long)out_size >= ySize + attSize) ? 1 : 0;
    float* attOut = Y + ySize;

    const float invscale = 1.0f / sqrtf((float)C_DM);
    const dim3 blk(256);

    constexpr int SMEM_T = STAGES * (A_WORDS + B_WORDS_T) * 4;   // 122880
    constexpr int SMEM_F = STAGES * (A_WORDS + B_WORDS_F) * 4;   // 108544
    cudaFuncSetAttribute(gemm_tf32<1, true,  false>, cudaFuncAttributeMaxDynamicSharedMemorySize, SMEM_F);
    cudaFuncSetAttribute(gemm_tf32<2, false, true >, cudaFuncAttributeMaxDynamicSharedMemorySize, SMEM_T);
    cudaFuncSetAttribute(gemm_tf32<0, true,  false>, cudaFuncAttributeMaxDynamicSharedMemorySize, SMEM_F);
    cudaFuncSetAttribute(gemm_tf32<1, false, false>, cudaFuncAttributeMaxDynamicSharedMemorySize, SMEM_F);

    // Weight prep: Weff = sum_h Wl blocks (rounded); round Wq/Wk/Wv (1MB each)
    wl_reduce_kernel<<<(C_DM * C_DM) / 256, 256>>>(Wl, pWeff);
    {
        const int n4 = C_DM * C_DM / 4;
        round_copy_kernel<<<n4 / 256, 256>>>((const float4*)Wq, (float4*)pWqR, n4);
        round_copy_kernel<<<n4 / 256, 256>>>((const float4*)Wk, (float4*)pWkR, n4);
        round_copy_kernel<<<n4 / 256, 256>>>((const float4*)Wv, (float4*)pWvR, n4);
    }

    // Projections: [8192,512] x [512,512] + bias, round result (B = W, [K,N])
    {
        dim3 grid(C_DM / BN, (C_B * C_SQ) / BM, 1);
        gemm_tf32<1, true, false><<<grid, blk, SMEM_F>>>(Q, pWqR, pQl,
            C_B * C_SQ, C_DM, C_DM, C_DM, C_DM, C_DM, 0, 0, 0,
            bq, nullptr, 0, 0.f);
        gemm_tf32<1, true, false><<<grid, blk, SMEM_F>>>(K, pWkR, pKl,
            C_B * C_SK, C_DM, C_DM, C_DM, C_DM, C_DM, 0, 0, 0,
            bk, nullptr, 0, 0.f);
        gemm_tf32<1, true, false><<<grid, blk, SMEM_F>>>(V, pWvR, pVl,
            C_B * C_SK, C_DM, C_DM, C_DM, C_DM, C_DM, 0, 0, 0,
            bv, nullptr, 0, 0.f);
    }

    // scores = Ql @ Kl^T * invscale + mask * (-1e9)   (B = Kl, [N,K])
    {
        dim3 grid(C_SK / BN, C_SQ / BM, C_B);
        gemm_tf32<2, false, true><<<grid, blk, SMEM_T>>>(pQl, pKl, pS,
            C_SQ, C_SK, C_DM, C_DM, C_DM, C_SK,
            (long long)C_SQ * C_DM, (long long)C_SK * C_DM,
            (long long)C_SQ * C_SK,
            nullptr, mask, C_SK, invscale);
    }

    // softmax: exact -> att_ws, rounded -> S
    {
        dim3 grid(C_SQ, C_B);
        softmax_kernel<<<grid, 256>>>(pS, attOut, writeAtt);
    }

    // head = att @ Vl   (B = Vl, [K,N]), round result
    {
        dim3 grid(C_DM / BN, C_SQ / BM, C_B);
        gemm_tf32<0, true, false><<<grid, blk, SMEM_F>>>(pS, pVl, pHead,
            C_SQ, C_DM, C_SK, C_SK, C_DM, C_DM,
            (long long)C_SQ * C_SK, (long long)C_SK * C_DM,
            (long long)C_SQ * C_DM,
            nullptr, nullptr, 0, 0.f);
    }

    // Y = head @ Weff + bl   (B = Weff, [K,N])
    {
        dim3 grid(C_DM / BN, (C_B * C_SQ) / BM, 1);
        gemm_tf32<1, false, false><<<grid, blk, SMEM_F>>>(pHead, pWeff, Y,
            C_B * C_SQ, C_DM, C_DM, C_DM, C_DM, C_DM, 0, 0, 0,
            bl, nullptr, 0, 0.f);
    }
}

// round 9
// speedup vs baseline: 3.3818x; 1.0901x over previous
#include <cuda_runtime.h>
#include <math.h>
#include <stdint.h>

// Problem constants
constexpr int C_DM = 512;
constexpr int C_H  = 8;
constexpr int C_B  = 8;
constexpr int C_SQ = 1024;
constexpr int C_SK = 1024;

// GEMM tiling: CTA 128x256x32, 8 warps (2x4), warp tile 64x64, 3-stage cp.async
constexpr int BM = 128;
constexpr int BN = 256;
constexpr int BK = 32;
constexpr int SA  = 36;    // smem row stride (words) for [row][k] tiles (A, and B when TB)
constexpr int SBF = 264;   // smem row stride (words) for [k][n] B tiles (TB=false)
constexpr int STAGES = 3;
constexpr int A_WORDS   = BM * SA;    // 4608
constexpr int B_WORDS_T = BN * SA;    // 9216
constexpr int B_WORDS_F = BK * SBF;   // 8448
constexpr int SMEM_T = STAGES * (A_WORDS + B_WORDS_T) * 4;  // 165888
constexpr int SMEM_F = STAGES * (A_WORDS + B_WORDS_F) * 4;  // 156672

// Scratch (allocation-free rule: __device__ globals)
__device__ float g_QKVl[3 * C_B * C_SQ * C_DM];   // Ql | Kl | Vl
__device__ float g_S   [C_B * (size_t)C_SQ * C_SK];
__device__ float g_head[C_B * C_SQ * C_DM];
__device__ float g_Weff[C_DM * C_DM];
__device__ float g_WqR [C_DM * C_DM];
__device__ float g_WkR [C_DM * C_DM];
__device__ float g_WvR [C_DM * C_DM];

__device__ __forceinline__ uint32_t f2tf32(float f) {
    uint32_t u;
    asm("cvt.rna.tf32.f32 %0, %1;" : "=r"(u) : "f"(f));
    return u;
}
__device__ __forceinline__ float roundtf(float f) {
    return __uint_as_float(f2tf32(f));
}

__device__ __forceinline__ uint32_t smem_u32(const void* p) {
    uint32_t a;
    asm("{ .reg .u64 t; cvta.to.shared.u64 t, %1; cvt.u32.u64 %0, t; }"
        : "=r"(a) : "l"(p));
    return a;
}

__device__ __forceinline__ void cp_async16(uint32_t dst, const void* src) {
    asm volatile("cp.async.cg.shared.global [%0], [%1], 16;"
                 :: "r"(dst), "l"(src));
}
#define CP_COMMIT() asm volatile("cp.async.commit_group;" ::: "memory")
#define CP_WAIT1()  asm volatile("cp.async.wait_group 1;"  ::: "memory")

__device__ __forceinline__ void mma_tf32(float c[4],
                                         const uint32_t a[4],
                                         const uint32_t b[2]) {
    asm volatile(
        "mma.sync.aligned.m16n8k8.row.col.f32.tf32.tf32.f32 "
        "{%0,%1,%2,%3}, {%4,%5,%6,%7}, {%8,%9}, {%0,%1,%2,%3};"
        : "+f"(c[0]), "+f"(c[1]), "+f"(c[2]), "+f"(c[3])
        : "r"(a[0]), "r"(a[1]), "r"(a[2]), "r"(a[3]),
          "r"(b[0]), "r"(b[1]));
}

// ---------------------------------------------------------------------------
// Elementwise tf32 round (vectorized) — only for 1MB weight matrices
// ---------------------------------------------------------------------------
__global__ __launch_bounds__(256)
void round_copy_kernel(const float4* __restrict__ in, float4* __restrict__ out,
                       int n4) {
    int i = blockIdx.x * blockDim.x + threadIdx.x;
    if (i < n4) {
        float4 v = in[i];
        v.x = roundtf(v.x); v.y = roundtf(v.y);
        v.z = roundtf(v.z); v.w = roundtf(v.w);
        out[i] = v;
    }
}

// ---------------------------------------------------------------------------
// Wl reduction: Weff[d, j] = sum_h Wl[h*DM + d, j], tf32-rounded.
// ---------------------------------------------------------------------------
__global__ void wl_reduce_kernel(const float* __restrict__ Wl,
                                 float* __restrict__ Weff) {
    int idx = blockIdx.x * blockDim.x + threadIdx.x;
    int d = idx / C_DM;
    int j = idx % C_DM;
    float s = 0.f;
#pragma unroll
    for (int h = 0; h < C_H; h++)
        s += Wl[((size_t)(h * C_DM + d)) * C_DM + j];
    Weff[idx] = roundtf(s);
}

// ---------------------------------------------------------------------------
// TF32 tensor-core GEMM, batched (z):
//   TB=true : C[M,N] = A[M,K] * B[N,K]^T   (B row-major [N,K])
//   TB=false: C[M,N] = A[M,K] * B[K,N]     (B row-major [K,N])
//   MODE 0: C = acc ; MODE 1: C = acc + bias[col]
//   MODE 2: C = acc*invscale + (float)mask[bz*maskStride + col] * (-1e9)
//   RND : round result to tf32 (when it feeds a later GEMM)
//   QKV : z selects operand set {A,A1,A2} x {B,B1,B2} x {bias,bias1,bias2}
// M%128==0, N%256==0, K%32==0, K>=64. 256 threads, 8 warps (2x4) of 64x64.
// ---------------------------------------------------------------------------
template <int MODE, bool RND, bool TB, bool QKV>
__global__ __launch_bounds__(256)
void gemm_tf32(const float* __restrict__ Ag, const float* __restrict__ Bg,
               float* __restrict__ Cg,
               int M, int N, int K, int lda, int ldb, int ldc,
               long long strideA, long long strideB, long long strideC,
               const float* __restrict__ bias,
               const int* __restrict__ mask, int maskStride, float invscale,
               const float* A1, const float* A2,
               const float* B1, const float* B2,
               const float* bias1, const float* bias2) {
    constexpr int B_WORDS = TB ? B_WORDS_T : B_WORDS_F;
    constexpr int STAGE_WORDS = A_WORDS + B_WORDS;

    extern __shared__ uint32_t sh[];
    const uint32_t smem_base = smem_u32(sh);

    const int bz = blockIdx.z;
    const float* A;
    const float* B;
    const float* bias_;
    float* C = Cg + bz * strideC;
    if (QKV) {
        A     = (bz == 0) ? Ag   : (bz == 1) ? A1    : A2;
        B     = (bz == 0) ? Bg   : (bz == 1) ? B1    : B2;
        bias_ = (bz == 0) ? bias : (bz == 1) ? bias1 : bias2;
    } else {
        A = Ag + bz * strideA;
        B = Bg + bz * strideB;
        bias_ = bias;
    }

    const int bm = blockIdx.y * BM;
    const int bn = blockIdx.x * BN;
    const int tid  = threadIdx.x;
    const int lane = tid & 31;
    const int warp = tid >> 5;
    const int wm = (warp & 1) * 64;
    const int wn = (warp >> 1) * 64;

    auto issue = [&](int s) {
        const int st = s % STAGES;
        const uint32_t sa = smem_base + st * STAGE_WORDS * 4;
        const uint32_t sb = sa + A_WORDS * 4;
        const int k0 = s * BK;
        // A: 128 rows x 8 16B-chunks = 1024, 4/thread
#pragma unroll
        for (int i = 0; i < 4; i++) {
            const int c = tid + i * 256;
            const int row = c >> 3, kc = (c & 7) * 4;
            cp_async16(sa + (row * SA + kc) * 4,
                       A + (size_t)(bm + row) * lda + k0 + kc);
        }
        if (TB) {
            // B [N,K]: 256 rows x 8 chunks = 2048, 8/thread -> smem [n][k] SA
#pragma unroll
            for (int i = 0; i < 8; i++) {
                const int c = tid + i * 256;
                const int row = c >> 3, kc = (c & 7) * 4;
                cp_async16(sb + (row * SA + kc) * 4,
                           B + (size_t)(bn + row) * ldb + k0 + kc);
            }
        } else {
            // B [K,N]: 32 rows x 64 chunks = 2048, 8/thread -> smem [k][n] SBF
#pragma unroll
            for (int i = 0; i < 8; i++) {
                const int c = tid + i * 256;
                const int row = c >> 6, nc = (c & 63) * 4;
                cp_async16(sb + (row * SBF + nc) * 4,
                           B + (size_t)(k0 + row) * ldb + bn + nc);
            }
        }
    };

    float acc[4][8][4];
#pragma unroll
    for (int mt = 0; mt < 4; mt++)
#pragma unroll
        for (int nt = 0; nt < 8; nt++)
#pragma unroll
            for (int r = 0; r < 4; r++) acc[mt][nt][r] = 0.f;

    auto compute = [&](int st) {
        const uint32_t* A0 = sh + st * STAGE_WORDS;
        const uint32_t* B0 = A0 + A_WORDS;
#pragma unroll
        for (int kg = 0; kg < BK / 8; kg++) {
            const int kk = kg * 8 + (lane & 3);
            uint32_t a[4][4];
#pragma unroll
            for (int mt = 0; mt < 4; mt++) {
                const uint32_t* p = A0 + (wm + mt * 16 + (lane >> 2)) * SA + kk;
                a[mt][0] = p[0];
                a[mt][1] = p[8 * SA];
                a[mt][2] = p[4];
                a[mt][3] = p[8 * SA + 4];
            }
            uint32_t b[8][2];
#pragma unroll
            for (int nt = 0; nt < 8; nt++) {
                if (TB) {
                    const uint32_t* p = B0 + (wn + nt * 8 + (lane >> 2)) * SA + kk;
                    b[nt][0] = p[0];
                    b[nt][1] = p[4];
                } else {
                    const uint32_t* p = B0 + kk * SBF + wn + nt * 8 + (lane >> 2);
                    b[nt][0] = p[0];
                    b[nt][1] = p[4 * SBF];
                }
            }
#pragma unroll
            for (int mt = 0; mt < 4; mt++)
#pragma unroll
                for (int nt = 0; nt < 8; nt++)
                    mma_tf32(acc[mt][nt], a[mt], b[nt]);
        }
    };

    const int NS = K / BK;
    issue(0); CP_COMMIT();
    issue(1); CP_COMMIT();

    for (int s = 0; s < NS; s++) {
        CP_WAIT1();
        __syncthreads();
        if (s + 2 < NS) issue(s + 2);
        CP_COMMIT();
        compute(s % STAGES);
    }

    // ---- epilogue ----
#pragma unroll
    for (int mt = 0; mt < 4; mt++) {
        const int row0 = bm + wm + mt * 16 + (lane >> 2);
#pragma unroll
        for (int nt = 0; nt < 8; nt++) {
            const int col = bn + wn + nt * 8 + (lane & 3) * 2;
#pragma unroll
            for (int half = 0; half < 2; half++) {
                const int row = row0 + half * 8;
                float v0 = acc[mt][nt][half * 2 + 0];
                float v1 = acc[mt][nt][half * 2 + 1];
                if (MODE == 1) {
                    v0 += bias_[col];
                    v1 += bias_[col + 1];
                } else if (MODE == 2) {
                    const int* mrow = mask + (size_t)bz * maskStride;
                    v0 = v0 * invscale + (float)mrow[col]     * -1e9f;
                    v1 = v1 * invscale + (float)mrow[col + 1] * -1e9f;
                }
                if (RND) { v0 = roundtf(v0); v1 = roundtf(v1); }
                float2 st; st.x = v0; st.y = v1;
                *reinterpret_cast<float2*>(&C[(size_t)row * ldc + col]) = st;
            }
        }
    }
}

// ---------------------------------------------------------------------------
// Row softmax over SK=1024. 256 threads, 4 elems/thread.
// Exact att -> attOut (replicated H times, streaming stores);
// tf32-rounded att -> S (AV GEMM's A operand).
// ---------------------------------------------------------------------------
__global__ __launch_bounds__(256)
void softmax_kernel(float* __restrict__ S, float* __restrict__ attOut,
                    int writeAtt) {
    const int q = blockIdx.x;
    const int b = blockIdx.y;
    const int tid = threadIdx.x;

    float* row = S + ((size_t)b * C_SQ + q) * C_SK;
    float4 x = *reinterpret_cast<const float4*>(&row[tid * 4]);

    __shared__ float red[256];
    float m = fmaxf(fmaxf(x.x, x.y), fmaxf(x.z, x.w));
    red[tid] = m;
    __syncthreads();
#pragma unroll
    for (int s = 128; s > 0; s >>= 1) {
        if (tid < s) red[tid] = fmaxf(red[tid], red[tid + s]);
        __syncthreads();
    }
    const float rowmax = red[0];
    __syncthreads();

    x.x = expf(x.x - rowmax);
    x.y = expf(x.y - rowmax);
    x.z = expf(x.z - rowmax);
    x.w = expf(x.w - rowmax);

    red[tid] = x.x + x.y + x.z + x.w;
    __syncthreads();
#pragma unroll
    for (int s = 128; s > 0; s >>= 1) {
        if (tid < s) red[tid] += red[tid + s];
        __syncthreads();
    }
    const float inv = 1.f / red[0];
    __syncthreads();

    x.x *= inv; x.y *= inv; x.z *= inv; x.w *= inv;

    if (writeAtt) {
        size_t base = ((size_t)b * C_H * C_SQ + q) * C_SK + tid * 4;
#pragma unroll
        for (int h = 0; h < C_H; h++)
            __stcs(reinterpret_cast<float4*>(&attOut[base + (size_t)h * C_SQ * C_SK]), x);
    }

    float4 xr;
    xr.x = roundtf(x.x); xr.y = roundtf(x.y);
    xr.z = roundtf(x.z); xr.w = roundtf(x.w);
    *reinterpret_cast<float4*>(&row[tid * 4]) = xr;
}

// ---------------------------------------------------------------------------
// Launch
// ---------------------------------------------------------------------------
extern "C" void kernel_launch(void* const* d_in, const int* in_sizes, int n_in,
                              void* d_out, int out_size) {
    const float* Q    = (const float*)d_in[0];
    const float* K    = (const float*)d_in[1];
    const float* V    = (const float*)d_in[2];
    const int*   mask = (const int*)  d_in[3];
    const float* Wq   = (const float*)d_in[4];
    const float* bq   = (const float*)d_in[5];
    const float* Wk   = (const float*)d_in[6];
    const float* bk   = (const float*)d_in[7];
    const float* Wv   = (const float*)d_in[8];
    const float* bv   = (const float*)d_in[9];
    const float* Wl   = (const float*)d_in[10];
    const float* bl   = (const float*)d_in[11];

    float *pQKV, *pS, *pHead, *pWeff, *pWqR, *pWkR, *pWvR;
    cudaGetSymbolAddress((void**)&pQKV,  g_QKVl);
    cudaGetSymbolAddress((void**)&pS,    g_S);
    cudaGetSymbolAddress((void**)&pHead, g_head);
    cudaGetSymbolAddress((void**)&pWeff, g_Weff);
    cudaGetSymbolAddress((void**)&pWqR,  g_WqR);
    cudaGetSymbolAddress((void**)&pWkR,  g_WkR);
    cudaGetSymbolAddress((void**)&pWvR,  g_WvR);

    const long long projSize = (long long)C_B * C_SQ * C_DM;   // 4,194,304
    float* pQl = pQKV;
    float* pKl = pQKV + projSize;
    float* pVl = pQKV + 2 * projSize;

    float* Y = (float*)d_out;
    const long long ySize   = projSize;
    const long long attSize = (long long)C_B * C_H * C_SQ * C_SK;
    const int writeAtt = ((long long)out_size >= ySize + attSize) ? 1 : 0;
    float* attOut = Y + ySize;

    const float invscale = 1.0f / sqrtf((float)C_DM);
    const dim3 blk(256);

    cudaFuncSetAttribute((const void*)gemm_tf32<1, true,  false, true >,
                         cudaFuncAttributeMaxDynamicSharedMemorySize, SMEM_F);
    cudaFuncSetAttribute((const void*)gemm_tf32<2, false, true,  false>,
                         cudaFuncAttributeMaxDynamicSharedMemorySize, SMEM_T);
    cudaFuncSetAttribute((const void*)gemm_tf32<0, true,  false, false>,
                         cudaFuncAttributeMaxDynamicSharedMemorySize, SMEM_F);
    cudaFuncSetAttribute((const void*)gemm_tf32<1, false, false, false>,
                         cudaFuncAttributeMaxDynamicSharedMemorySize, SMEM_F);

    // Weight prep: Weff = sum_h Wl blocks (rounded); round Wq/Wk/Wv (1MB each)
    wl_reduce_kernel<<<(C_DM * C_DM) / 256, 256>>>(Wl, pWeff);
    {
        const int n4 = C_DM * C_DM / 4;
        round_copy_kernel<<<n4 / 256, 256>>>((const float4*)Wq, (float4*)pWqR, n4);
        round_copy_kernel<<<n4 / 256, 256>>>((const float4*)Wk, (float4*)pWkR, n4);
        round_copy_kernel<<<n4 / 256, 256>>>((const float4*)Wv, (float4*)pWvR, n4);
    }

    // Fused QKV projections: z in {0,1,2} -> (Q,Wq,bq), (K,Wk,bk), (V,Wv,bv)
    {
        dim3 grid(C_DM / BN, (C_B * C_SQ) / BM, 3);
        gemm_tf32<1, true, false, true><<<grid, blk, SMEM_F>>>(
            Q, pWqR, pQKV,
            C_B * C_SQ, C_DM, C_DM, C_DM, C_DM, C_DM,
            0, 0, projSize,
            bq, nullptr, 0, 0.f,
            K, V, pWkR, pWvR, bk, bv);
    }

    // scores = Ql @ Kl^T * invscale + mask * (-1e9)   (B = Kl, [N,K])
    {
        dim3 grid(C_SK / BN, C_SQ / BM, C_B);
        gemm_tf32<2, false, true, false><<<grid, blk, SMEM_T>>>(
            pQl, pKl, pS,
            C_SQ, C_SK, C_DM, C_DM, C_DM, C_SK,
            (long long)C_SQ * C_DM, (long long)C_SK * C_DM,
            (long long)C_SQ * C_SK,
            nullptr, mask, C_SK, invscale,
            nullptr, nullptr, nullptr, nullptr, nullptr, nullptr);
    }

    // softmax: exact -> att_ws, rounded -> S
    {
        dim3 grid(C_SQ, C_B);
        softmax_kernel<<<grid, 256>>>(pS, attOut, writeAtt);
    }

    // head = att @ Vl   (B = Vl, [K,N]), round result
    {
        dim3 grid(C_DM / BN, C_SQ / BM, C_B);
        gemm_tf32<0, true, false, false><<<grid, blk, SMEM_F>>>(
            pS, pVl, pHead,
            C_SQ, C_DM, C_SK, C_SK, C_DM, C_DM,
            (long long)C_SQ * C_SK, (long long)C_SK * C_DM,
            (long long)C_SQ * C_DM,
            nullptr, nullptr, 0, 0.f,
            nullptr, nullptr, nullptr, nullptr, nullptr, nullptr);
    }

    // Y = head @ Weff + bl   (B = Weff, [K,N])
    {
        dim3 grid(C_DM / BN, (C_B * C_SQ) / BM, 1);
        gemm_tf32<1, false, false, false><<<grid, blk, SMEM_F>>>(
            pHead, pWeff, Y,
            C_B * C_SQ, C_DM, C_DM, C_DM, C_DM, C_DM, 0, 0, 0,
            bl, nullptr, 0, 0.f,
            nullptr, nullptr, nullptr, nullptr, nullptr, nullptr);
    }
}